// round 9
// baseline (speedup 1.0000x reference)
#include <cuda_runtime.h>
#include <cuda_bf16.h>
#include <math.h>

#define N_NODES 50000
#define N_EDGES 800000
#define FEAT    128
#define HEADS   8
#define CH      16

// ---------------- scratch (no allocs; referenced ONLY from device code) ----------
static __device__ __align__(16) float g_bufA[(size_t)N_NODES * FEAT];
static __device__ __align__(16) float g_bufB[(size_t)N_NODES * FEAT];
static __device__ float g_alsrc[N_NODES * HEADS];
static __device__ float g_aldst[N_NODES * HEADS];
static __device__ int   g_rowptr[N_NODES + 1];
static __device__ int   g_cnt[N_NODES];
static __device__ int   g_fill[N_NODES];
static __device__ int   g_col[N_EDGES];
static __device__ int   g_incl[N_NODES];
static __device__ int   g_bsum[64];
static __device__ float g_gsum[16];
static __device__ int   g_is64;

__device__ __forceinline__ float lrelu02(float x) { return x > 0.f ? x : 0.2f * x; }
__device__ __forceinline__ float elu1(float x)    { return x > 0.f ? x : (__expf(x) - 1.f); }
__device__ __forceinline__ int   clampN(int v)    { return v < 0 ? 0 : (v >= N_NODES ? N_NODES - 1 : v); }

// ---------------- edge dtype probe ----------------
__global__ void k_detect(const unsigned int* __restrict__ w) {
    __shared__ unsigned int sh[1024];
    int t = threadIdx.x;
    sh[t] = w[2 * t + 1];
    __syncthreads();
    for (int off = 512; off > 0; off >>= 1) {
        if (t < off) sh[t] |= sh[t + off];
        __syncthreads();
    }
    if (t == 0) g_is64 = (sh[0] == 0u) ? 1 : 0;
}

__device__ __forceinline__ int load_src(const void* eiv, int e) {
    return clampN(g_is64 ? (int)((const long long*)eiv)[e] : ((const int*)eiv)[e]);
}
__device__ __forceinline__ int load_dst(const void* eiv, int e) {
    return clampN(g_is64 ? (int)((const long long*)eiv)[N_EDGES + e]
                         : ((const int*)eiv)[N_EDGES + e]);
}

// ---------------- CSR build ----------------
__global__ void k_zero() {
    int i = blockIdx.x * blockDim.x + threadIdx.x;
    if (i < N_NODES) { g_cnt[i] = 0; g_fill[i] = 0; }
    if (i < 16) g_gsum[i] = 0.f;
}

__global__ void k_count(const void* __restrict__ eiv) {
    int e = blockIdx.x * blockDim.x + threadIdx.x;
    if (e >= N_EDGES) return;
    atomicAdd(&g_cnt[load_dst(eiv, e)], 1);
}

__global__ void k_scan1() {
    __shared__ int sh[1024];
    int t = threadIdx.x;
    int g = blockIdx.x * 1024 + t;
    int v = (g < N_NODES) ? g_cnt[g] : 0;
    sh[t] = v;
    __syncthreads();
    for (int off = 1; off < 1024; off <<= 1) {
        int add = (t >= off) ? sh[t - off] : 0;
        __syncthreads();
        sh[t] += add;
        __syncthreads();
    }
    if (g < N_NODES) g_incl[g] = sh[t];
    if (t == 1023) g_bsum[blockIdx.x] = sh[1023];
}

__global__ void k_scan2(int nchunks) {
    if (threadIdx.x == 0) {
        int acc = 0;
        for (int i = 0; i < nchunks; i++) { int v = g_bsum[i]; g_bsum[i] = acc; acc += v; }
    }
}

__global__ void k_scan3() {
    int i = blockIdx.x * blockDim.x + threadIdx.x;
    if (i >= N_NODES) return;
    g_rowptr[i + 1] = g_incl[i] + g_bsum[i >> 10];
    if (i == 0) g_rowptr[0] = 0;
}

__global__ void k_scatter(const void* __restrict__ eiv) {
    int e = blockIdx.x * blockDim.x + threadIdx.x;
    if (e >= N_EDGES) return;
    int d = load_dst(eiv, e);
    int pos = g_rowptr[d] + atomicAdd(&g_fill[d], 1);
    g_col[pos] = load_src(eiv, e);
}

// ---------------- tf32 helpers ----------------
__device__ __forceinline__ void split4(float4 v, float4& hi, float4& lo) {
    hi.x = __uint_as_float(__float_as_uint(v.x) & 0xffffe000u); lo.x = v.x - hi.x;
    hi.y = __uint_as_float(__float_as_uint(v.y) & 0xffffe000u); lo.y = v.y - hi.y;
    hi.z = __uint_as_float(__float_as_uint(v.z) & 0xffffe000u); lo.z = v.z - hi.z;
    hi.w = __uint_as_float(__float_as_uint(v.w) & 0xffffe000u); lo.w = v.w - hi.w;
}

__device__ __forceinline__ void mma8(float* d,
                                     unsigned a0, unsigned a1, unsigned a2, unsigned a3,
                                     unsigned b0, unsigned b1) {
    asm volatile(
        "mma.sync.aligned.m16n8k8.row.col.f32.tf32.tf32.f32 "
        "{%0,%1,%2,%3}, {%4,%5,%6,%7}, {%8,%9}, {%0,%1,%2,%3};\n"
        : "+f"(d[0]), "+f"(d[1]), "+f"(d[2]), "+f"(d[3])
        : "r"(a0), "r"(a1), "r"(a2), "r"(a3), "r"(b0), "r"(b1));
}

// ---------------- tensor-core GEMM (3xTF32) — 32x64 warp tiles ----------------
// g_bufA[M,128] = A[M,K] @ W[K,128]; also writes g_alsrc/g_aldst per (row,head).
// BM=128, BN=128, BK=16; 8 warps as 4 warp-rows x 2 warp-cols; each warp owns
// 32 rows x 64 cols (2 m16 tiles x 8 n8 tiles). W smem is fragment-major:
// WhS[k][g*16 + j] = W[k][j*8 + g]; a warp's 8 j-values are contiguous.
template <int SRC>
__global__ __launch_bounds__(256, 2) void k_gemm(const float* __restrict__ Ain,
                                                 const float* __restrict__ W,
                                                 const float* __restrict__ a_src,
                                                 const float* __restrict__ a_dst,
                                                 int M, int K) {
    const float* __restrict__ A = (SRC == 0) ? Ain : (const float*)g_bufB;
    float* __restrict__ C = g_bufA;

    __shared__ __align__(16) float Ah[128][20];
    __shared__ __align__(16) float Al[128][20];
    __shared__ __align__(16) float WhS[16][132];
    __shared__ __align__(16) float WlS[16][132];

    const int tid  = threadIdx.x;
    const int lane = tid & 31;
    const int warp = tid >> 5;
    const int q    = lane & 3;
    const int g    = lane >> 2;
    const int wm   = (warp >> 1) * 32;   // warp row base (0,32,64,96)
    const int wn   = (warp & 1) * 8;     // warp n-tile base (0 or 8)
    const int row0 = blockIdx.x * 128;

    float d[2][8][4];
#pragma unroll
    for (int mt = 0; mt < 2; mt++)
#pragma unroll
        for (int j = 0; j < 8; j++)
#pragma unroll
            for (int i = 0; i < 4; i++) d[mt][j][i] = 0.f;

    // staging maps
    const int a_row = tid >> 1;
    const int a_cb  = (tid & 1) * 8;
    const int w_r   = tid >> 4;
    const int w_cb  = (tid & 15) * 8;
    const int w_j0  = w_cb >> 3;

    const int gr   = row0 + a_row;
    const bool gok = (gr < M);
    const int nkt  = K >> 4;

    float4 av0 = make_float4(0.f, 0.f, 0.f, 0.f), av1 = av0;
    if (gok) {
        av0 = *(const float4*)&A[(size_t)gr * K + a_cb];
        av1 = *(const float4*)&A[(size_t)gr * K + a_cb + 4];
    }
    float4 wv0 = *(const float4*)&W[(size_t)w_r * 128 + w_cb];
    float4 wv1 = *(const float4*)&W[(size_t)w_r * 128 + w_cb + 4];

    for (int kt = 0; kt < nkt; kt++) {
        float4 h0, l0, h1, l1;
        split4(av0, h0, l0); split4(av1, h1, l1);
        *(float4*)&Ah[a_row][a_cb]     = h0;  *(float4*)&Al[a_row][a_cb]     = l0;
        *(float4*)&Ah[a_row][a_cb + 4] = h1;  *(float4*)&Al[a_row][a_cb + 4] = l1;
        split4(wv0, h0, l0); split4(wv1, h1, l1);
        {
            float* dh = &WhS[w_r][w_j0];
            float* dl = &WlS[w_r][w_j0];
            dh[0*16] = h0.x; dh[1*16] = h0.y; dh[2*16] = h0.z; dh[3*16] = h0.w;
            dh[4*16] = h1.x; dh[5*16] = h1.y; dh[6*16] = h1.z; dh[7*16] = h1.w;
            dl[0*16] = l0.x; dl[1*16] = l0.y; dl[2*16] = l0.z; dl[3*16] = l0.w;
            dl[4*16] = l1.x; dl[5*16] = l1.y; dl[6*16] = l1.z; dl[7*16] = l1.w;
        }
        __syncthreads();

        if (kt + 1 < nkt) {
            int k0g = (kt + 1) << 4;
            av0 = make_float4(0.f, 0.f, 0.f, 0.f); av1 = av0;
            if (gok) {
                av0 = *(const float4*)&A[(size_t)gr * K + k0g + a_cb];
                av1 = *(const float4*)&A[(size_t)gr * K + k0g + a_cb + 4];
            }
            wv0 = *(const float4*)&W[(size_t)(k0g + w_r) * 128 + w_cb];
            wv1 = *(const float4*)&W[(size_t)(k0g + w_r) * 128 + w_cb + 4];
        }

#pragma unroll
        for (int ks = 0; ks < 2; ks++) {
            const int k0 = ks * 8;
            // W fragments: 8 contiguous j's -> 2 float4 per (row, split)
            float4 vh0a = *(const float4*)&WhS[k0 + q][g * 16 + wn];
            float4 vh0b = *(const float4*)&WhS[k0 + q][g * 16 + wn + 4];
            float4 vh1a = *(const float4*)&WhS[k0 + q + 4][g * 16 + wn];
            float4 vh1b = *(const float4*)&WhS[k0 + q + 4][g * 16 + wn + 4];
            float4 vl0a = *(const float4*)&WlS[k0 + q][g * 16 + wn];
            float4 vl0b = *(const float4*)&WlS[k0 + q][g * 16 + wn + 4];
            float4 vl1a = *(const float4*)&WlS[k0 + q + 4][g * 16 + wn];
            float4 vl1b = *(const float4*)&WlS[k0 + q + 4][g * 16 + wn + 4];
            const float* bh0 = (const float*)&vh0a;  // [j0..j3]
            const float* bh0b = (const float*)&vh0b; // [j4..j7]
            const float* bh1 = (const float*)&vh1a;
            const float* bh1b = (const float*)&vh1b;
            const float* bl0 = (const float*)&vl0a;
            const float* bl0b = (const float*)&vl0b;
            const float* bl1 = (const float*)&vl1a;
            const float* bl1b = (const float*)&vl1b;
#pragma unroll
            for (int mt = 0; mt < 2; mt++) {
                const int mb = wm + mt * 16;
                unsigned ah0 = __float_as_uint(Ah[mb + g][k0 + q]);
                unsigned ah1 = __float_as_uint(Ah[mb + g + 8][k0 + q]);
                unsigned ah2 = __float_as_uint(Ah[mb + g][k0 + q + 4]);
                unsigned ah3 = __float_as_uint(Ah[mb + g + 8][k0 + q + 4]);
                unsigned al0 = __float_as_uint(Al[mb + g][k0 + q]);
                unsigned al1 = __float_as_uint(Al[mb + g + 8][k0 + q]);
                unsigned al2 = __float_as_uint(Al[mb + g][k0 + q + 4]);
                unsigned al3 = __float_as_uint(Al[mb + g + 8][k0 + q + 4]);
#pragma unroll
                for (int j = 0; j < 8; j++) {
                    unsigned b0 = __float_as_uint(j < 4 ? bh0[j] : bh0b[j - 4]);
                    unsigned b1 = __float_as_uint(j < 4 ? bh1[j] : bh1b[j - 4]);
                    unsigned c0 = __float_as_uint(j < 4 ? bl0[j] : bl0b[j - 4]);
                    unsigned c1 = __float_as_uint(j < 4 ? bl1[j] : bl1b[j - 4]);
                    mma8(d[mt][j], ah0, ah1, ah2, ah3, b0, b1);
                    mma8(d[mt][j], al0, al1, al2, al3, b0, b1);
                    mma8(d[mt][j], ah0, ah1, ah2, ah3, c0, c1);
                }
            }
        }
        __syncthreads();
    }

    // write C
#pragma unroll
    for (int mt = 0; mt < 2; mt++) {
        const int r0 = row0 + wm + mt * 16 + g;
        const int r1 = r0 + 8;
#pragma unroll
        for (int j = 0; j < 8; j++) {
            int col = (wn + j) * 8 + 2 * q;
            if (r0 < M) *(float2*)&C[(size_t)r0 * 128 + col] = make_float2(d[mt][j][0], d[mt][j][1]);
            if (r1 < M) *(float2*)&C[(size_t)r1 * 128 + col] = make_float2(d[mt][j][2], d[mt][j][3]);
        }
    }

    // fused attention logits: this warp covers heads wn/2 .. wn/2+3 (4 heads)
#pragma unroll
    for (int hl = 0; hl < 4; hl++) {
        const int hd = (wn >> 1) + hl;
#pragma unroll
        for (int mt = 0; mt < 2; mt++) {
            float ss0 = 0.f, ds0 = 0.f, ss1 = 0.f, ds1 = 0.f;
#pragma unroll
            for (int jj = 0; jj < 2; jj++) {
                int j = hl * 2 + jj;           // local j
                int c = jj * 8 + 2 * q;        // col within head
                float as0 = a_src[hd * CH + c], as1 = a_src[hd * CH + c + 1];
                float ad0 = a_dst[hd * CH + c], ad1 = a_dst[hd * CH + c + 1];
                ss0 += d[mt][j][0] * as0 + d[mt][j][1] * as1;
                ds0 += d[mt][j][0] * ad0 + d[mt][j][1] * ad1;
                ss1 += d[mt][j][2] * as0 + d[mt][j][3] * as1;
                ds1 += d[mt][j][2] * ad0 + d[mt][j][3] * ad1;
            }
            ss0 += __shfl_xor_sync(0xffffffffu, ss0, 1);
            ss0 += __shfl_xor_sync(0xffffffffu, ss0, 2);
            ds0 += __shfl_xor_sync(0xffffffffu, ds0, 1);
            ds0 += __shfl_xor_sync(0xffffffffu, ds0, 2);
            ss1 += __shfl_xor_sync(0xffffffffu, ss1, 1);
            ss1 += __shfl_xor_sync(0xffffffffu, ss1, 2);
            ds1 += __shfl_xor_sync(0xffffffffu, ds1, 1);
            ds1 += __shfl_xor_sync(0xffffffffu, ds1, 2);
            if (q == 0) {
                const int r0 = row0 + wm + mt * 16 + g;
                const int r1 = r0 + 8;
                if (r0 < M) { g_alsrc[r0 * 8 + hd] = ss0; g_aldst[r0 * 8 + hd] = ds0; }
                if (r1 < M) { g_alsrc[r1 * 8 + hd] = ss1; g_aldst[r1 * 8 + hd] = ds1; }
            }
        }
    }
}

// ---------------- per-node softmax + aggregation (one warp / node), pipelined ----
template <int MODE>
__global__ void k_agg(const float* __restrict__ bias, float* __restrict__ outp,
                      const float* __restrict__ an_w1, const float* __restrict__ an_b1,
                      const float* __restrict__ an_w2, const float* __restrict__ an_b2) {
    int gw = (blockIdx.x * blockDim.x + threadIdx.x) >> 5;
    if (gw >= N_NODES) return;
    int lane = threadIdx.x & 31;
    int d = gw;
    const float* __restrict__ h = g_bufA;
    float* __restrict__ out = (MODE == 0) ? (float*)g_bufB : outp;
    int beg = g_rowptr[d], end = g_rowptr[d + 1];

    float adst = 0.f, asrc_self = 0.f;
    if (lane < 8) {
        adst      = g_aldst[d * 8 + lane];
        asrc_self = g_alsrc[d * 8 + lane];
    }
    const int head = lane >> 2;
    float den = 0.f;
    float4 acc = make_float4(0.f, 0.f, 0.f, 0.f);

    int i = beg;
    int sA = (i < end) ? g_col[i] : -1;
    float alA = 0.f;
    float4 hA = make_float4(0.f, 0.f, 0.f, 0.f);
    if (sA >= 0) {
        if (lane < 8) alA = g_alsrc[sA * 8 + lane];
        hA = *(const float4*)&h[(size_t)sA * FEAT + lane * 4];
    }
    {   // self loop
        float p = 0.f;
        if (lane < 8) { p = __expf(lrelu02(asrc_self + adst)); den += p; }
        float w = __shfl_sync(0xffffffffu, p, head);
        float4 hv = *(const float4*)&h[(size_t)d * FEAT + lane * 4];
        acc.x += hv.x * w; acc.y += hv.y * w; acc.z += hv.z * w; acc.w += hv.w * w;
    }
    while (sA >= 0) {
        int ii = i + 1;
        int sB = (ii < end) ? g_col[ii] : -1;
        float alB = 0.f;
        float4 hB = make_float4(0.f, 0.f, 0.f, 0.f);
        if (sB >= 0) {
            if (lane < 8) alB = g_alsrc[sB * 8 + lane];
            hB = *(const float4*)&h[(size_t)sB * FEAT + lane * 4];
        }
        float p = 0.f;
        if (lane < 8) { p = __expf(lrelu02(alA + adst)); den += p; }
        float w = __shfl_sync(0xffffffffu, p, head);
        acc.x += hA.x * w; acc.y += hA.y * w; acc.z += hA.z * w; acc.w += hA.w * w;
        sA = sB; alA = alB; hA = hB; i = ii;
    }
    float denw = __shfl_sync(0xffffffffu, den, head);
    float inv = 1.f / denw;
    acc.x *= inv; acc.y *= inv; acc.z *= inv; acc.w *= inv;

    if (MODE == 0) {
        float4 bb = *(const float4*)&bias[lane * 4];
        acc.x = elu1(acc.x + bb.x);
        acc.y = elu1(acc.y + bb.y);
        acc.z = elu1(acc.z + bb.z);
        acc.w = elu1(acc.w + bb.w);
        *(float4*)&out[(size_t)d * FEAT + lane * 4] = acc;
    } else {
#pragma unroll
        for (int off = 4; off <= 16; off <<= 1) {
            acc.x += __shfl_xor_sync(0xffffffffu, acc.x, off);
            acc.y += __shfl_xor_sync(0xffffffffu, acc.y, off);
            acc.z += __shfl_xor_sync(0xffffffffu, acc.z, off);
            acc.w += __shfl_xor_sync(0xffffffffu, acc.w, off);
        }
        float4 bb = *(const float4*)&bias[(lane & 3) * 4];
        float4 r;
        r.x = acc.x * 0.125f + bb.x;
        r.y = acc.y * 0.125f + bb.y;
        r.z = acc.z * 0.125f + bb.z;
        r.w = acc.w * 0.125f + bb.w;
        if (lane < 4) *(float4*)&out[(size_t)d * CH + lane * 4] = r;

        // fused anomaly head: 16 -> 32 relu -> 1 sigmoid
        float hv[16];
#pragma unroll
        for (int c = 0; c < 16; c++) {
            float comp = ((c & 3) == 0) ? r.x : ((c & 3) == 1) ? r.y
                        : ((c & 3) == 2) ? r.z : r.w;
            hv[c] = __shfl_sync(0xffffffffu, comp, c >> 2);
        }
        float t = an_b1[lane];
#pragma unroll
        for (int c = 0; c < 16; c++) t += hv[c] * an_w1[c * 32 + lane];
        float contrib = fmaxf(t, 0.f) * an_w2[lane];
#pragma unroll
        for (int off = 16; off >= 1; off >>= 1)
            contrib += __shfl_xor_sync(0xffffffffu, contrib, off);
        if (lane == 0)
            out[800000 + d] = 1.f / (1.f + __expf(-(contrib + an_b2[0])));
    }
}

// ---------------- graph mean ----------------
__global__ void k_gsum(const float* __restrict__ hout) {
    __shared__ float sh[256];
    int tid = threadIdx.x;
    float s = 0.f;
    size_t total = (size_t)N_NODES * 16;
    size_t stride = (size_t)gridDim.x * 256;
    for (size_t idx = (size_t)blockIdx.x * 256 + tid; idx < total; idx += stride)
        s += hout[idx];
    sh[tid] = s;
    __syncthreads();
    for (int off = 128; off >= 16; off >>= 1) {
        if (tid < off) sh[tid] += sh[tid + off];
        __syncthreads();
    }
    if (tid < 16) atomicAdd(&g_gsum[tid], sh[tid]);
}

// ---------------- graph classifier ----------------
__global__ void k_final(const float* __restrict__ w1, const float* __restrict__ b1,
                        const float* __restrict__ w2, const float* __restrict__ b2,
                        float* __restrict__ out) {
    __shared__ float emb[16];
    __shared__ float hid[64];
    int t = threadIdx.x;
    if (t < 16) {
        float e = g_gsum[t] * (1.f / (float)N_NODES);
        emb[t] = e;
        out[850000 + t] = e;
    }
    __syncthreads();
    float s = b1[t];
#pragma unroll
    for (int c = 0; c < 16; c++) s += emb[c] * w1[c * 64 + t];
    hid[t] = fmaxf(s, 0.f);
    __syncthreads();
    if (t < 2) {
        float r = b2[t];
#pragma unroll
        for (int u = 0; u < 64; u++) r += hid[u] * w2[u * 2 + t];
        out[850016 + t] = r;
    }
}

// ---------------- launch ----------------
extern "C" void kernel_launch(void* const* d_in, const int* in_sizes, int n_in,
                              void* d_out, int out_size) {
    const float* x      = (const float*)d_in[0];
    const void*  ei     = d_in[1];
    const float* W1     = (const float*)d_in[2];
    const float* a1s    = (const float*)d_in[3];
    const float* a1d    = (const float*)d_in[4];
    const float* b1     = (const float*)d_in[5];
    const float* W2     = (const float*)d_in[6];
    const float* a2s    = (const float*)d_in[7];
    const float* a2d    = (const float*)d_in[8];
    const float* b2     = (const float*)d_in[9];
    const float* W3     = (const float*)d_in[10];
    const float* a3s    = (const float*)d_in[11];
    const float* a3d    = (const float*)d_in[12];
    const float* b3     = (const float*)d_in[13];
    const float* cls_w1 = (const float*)d_in[14];
    const float* cls_b1 = (const float*)d_in[15];
    const float* cls_w2 = (const float*)d_in[16];
    const float* cls_b2 = (const float*)d_in[17];
    const float* an_w1  = (const float*)d_in[18];
    const float* an_b1  = (const float*)d_in[19];
    const float* an_w2  = (const float*)d_in[20];
    const float* an_b2  = (const float*)d_in[21];
    float* out = (float*)d_out;

    const int TB = 256;
    const int nodeBlocks = (N_NODES + TB - 1) / TB;
    const int edgeBlocks = (N_EDGES + TB - 1) / TB;
    const int aggBlocks  = (N_NODES * 32 + TB - 1) / TB;
    const int gemmBlocks = (N_NODES + 127) / 128;  // 391
    const int nchunks    = (N_NODES + 1023) / 1024;

    // layer-1 GEMM kept in the profiled slot (4th launch)
    k_detect<<<1, 1024>>>((const unsigned int*)ei);
    k_zero<<<nodeBlocks, TB>>>();
    k_count<<<edgeBlocks, TB>>>(ei);
    k_gemm<0><<<gemmBlocks, TB>>>(x, W1, a1s, a1d, N_NODES, 256);   // profiled
    k_scan1<<<nchunks, 1024>>>();
    k_scan2<<<1, 32>>>(nchunks);
    k_scan3<<<nodeBlocks, TB>>>();
    k_scatter<<<edgeBlocks, TB>>>(ei);

    k_agg<0><<<aggBlocks, TB>>>(b1, nullptr, nullptr, nullptr, nullptr, nullptr);

    k_gemm<1><<<gemmBlocks, TB>>>(nullptr, W2, a2s, a2d, N_NODES, 128);
    k_agg<0><<<aggBlocks, TB>>>(b2, nullptr, nullptr, nullptr, nullptr, nullptr);

    k_gemm<1><<<gemmBlocks, TB>>>(nullptr, W3, a3s, a3d, N_NODES, 128);
    k_agg<1><<<aggBlocks, TB>>>(b3, out, an_w1, an_b1, an_w2, an_b2);

    k_gsum<<<64, TB>>>(out);
    k_final<<<1, 64>>>(cls_w1, cls_b1, cls_w2, cls_b2, out);
}

// round 10
// speedup vs baseline: 1.0265x; 1.0265x over previous
#include <cuda_runtime.h>
#include <cuda_bf16.h>
#include <cuda_fp16.h>
#include <math.h>

#define N_NODES 50000
#define N_EDGES 800000
#define FEAT    128
#define HEADS   8
#define CH      16

// ---------------- scratch (no allocs; referenced ONLY from device code) ----------
static __device__ __align__(16) float  g_bufB[(size_t)N_NODES * FEAT];  // agg out (fp32)
static __device__ __align__(16) __half g_bufH[(size_t)N_NODES * FEAT];  // h (fp16, gathered)
static __device__ float g_alsrc[N_NODES * HEADS];
static __device__ float g_aldst[N_NODES * HEADS];
static __device__ int   g_rowptr[N_NODES + 1];
static __device__ int   g_cnt[N_NODES];
static __device__ int   g_fill[N_NODES];
static __device__ int   g_col[N_EDGES];
static __device__ int   g_incl[N_NODES];
static __device__ int   g_bsum[64];
static __device__ float g_gsum[16];
static __device__ int   g_is64;

__device__ __forceinline__ float lrelu02(float x) { return x > 0.f ? x : 0.2f * x; }
__device__ __forceinline__ float elu1(float x)    { return x > 0.f ? x : (__expf(x) - 1.f); }
__device__ __forceinline__ int   clampN(int v)    { return v < 0 ? 0 : (v >= N_NODES ? N_NODES - 1 : v); }

// ---------------- edge dtype probe ----------------
__global__ void k_detect(const unsigned int* __restrict__ w) {
    __shared__ unsigned int sh[1024];
    int t = threadIdx.x;
    sh[t] = w[2 * t + 1];
    __syncthreads();
    for (int off = 512; off > 0; off >>= 1) {
        if (t < off) sh[t] |= sh[t + off];
        __syncthreads();
    }
    if (t == 0) g_is64 = (sh[0] == 0u) ? 1 : 0;
}

__device__ __forceinline__ int load_src(const void* eiv, int e) {
    return clampN(g_is64 ? (int)((const long long*)eiv)[e] : ((const int*)eiv)[e]);
}
__device__ __forceinline__ int load_dst(const void* eiv, int e) {
    return clampN(g_is64 ? (int)((const long long*)eiv)[N_EDGES + e]
                         : ((const int*)eiv)[N_EDGES + e]);
}

// ---------------- CSR build ----------------
__global__ void k_zero() {
    int i = blockIdx.x * blockDim.x + threadIdx.x;
    if (i < N_NODES) { g_cnt[i] = 0; g_fill[i] = 0; }
    if (i < 16) g_gsum[i] = 0.f;
}

__global__ void k_count(const void* __restrict__ eiv) {
    int e = blockIdx.x * blockDim.x + threadIdx.x;
    if (e >= N_EDGES) return;
    atomicAdd(&g_cnt[load_dst(eiv, e)], 1);
}

__global__ void k_scan1() {
    __shared__ int sh[1024];
    int t = threadIdx.x;
    int g = blockIdx.x * 1024 + t;
    int v = (g < N_NODES) ? g_cnt[g] : 0;
    sh[t] = v;
    __syncthreads();
    for (int off = 1; off < 1024; off <<= 1) {
        int add = (t >= off) ? sh[t - off] : 0;
        __syncthreads();
        sh[t] += add;
        __syncthreads();
    }
    if (g < N_NODES) g_incl[g] = sh[t];
    if (t == 1023) g_bsum[blockIdx.x] = sh[1023];
}

__global__ void k_scan2(int nchunks) {
    if (threadIdx.x == 0) {
        int acc = 0;
        for (int i = 0; i < nchunks; i++) { int v = g_bsum[i]; g_bsum[i] = acc; acc += v; }
    }
}

__global__ void k_scan3() {
    int i = blockIdx.x * blockDim.x + threadIdx.x;
    if (i >= N_NODES) return;
    g_rowptr[i + 1] = g_incl[i] + g_bsum[i >> 10];
    if (i == 0) g_rowptr[0] = 0;
}

__global__ void k_scatter(const void* __restrict__ eiv) {
    int e = blockIdx.x * blockDim.x + threadIdx.x;
    if (e >= N_EDGES) return;
    int d = load_dst(eiv, e);
    int pos = g_rowptr[d] + atomicAdd(&g_fill[d], 1);
    g_col[pos] = load_src(eiv, e);
}

// ---------------- tf32 helpers ----------------
__device__ __forceinline__ void split4(float4 v, float4& hi, float4& lo) {
    hi.x = __uint_as_float(__float_as_uint(v.x) & 0xffffe000u); lo.x = v.x - hi.x;
    hi.y = __uint_as_float(__float_as_uint(v.y) & 0xffffe000u); lo.y = v.y - hi.y;
    hi.z = __uint_as_float(__float_as_uint(v.z) & 0xffffe000u); lo.z = v.z - hi.z;
    hi.w = __uint_as_float(__float_as_uint(v.w) & 0xffffe000u); lo.w = v.w - hi.w;
}

__device__ __forceinline__ void mma8(float* d,
                                     unsigned a0, unsigned a1, unsigned a2, unsigned a3,
                                     unsigned b0, unsigned b1) {
    asm volatile(
        "mma.sync.aligned.m16n8k8.row.col.f32.tf32.tf32.f32 "
        "{%0,%1,%2,%3}, {%4,%5,%6,%7}, {%8,%9}, {%0,%1,%2,%3};\n"
        : "+f"(d[0]), "+f"(d[1]), "+f"(d[2]), "+f"(d[3])
        : "r"(a0), "r"(a1), "r"(a2), "r"(a3), "r"(b0), "r"(b1));
}

// ---------------- tensor-core GEMM (3xTF32, round-8 config) ----------------
// h = A @ W written as fp16 to g_bufH; fused logits to g_alsrc/g_aldst (fp32).
// BM=128, BN=128, BK=16; 8 warps, warp w owns rows w*16..w*16+15, all 128 cols.
template <int SRC>
__global__ __launch_bounds__(256, 2) void k_gemm(const float* __restrict__ Ain,
                                                 const float* __restrict__ W,
                                                 const float* __restrict__ a_src,
                                                 const float* __restrict__ a_dst,
                                                 int M, int K) {
    const float* __restrict__ A = (SRC == 0) ? Ain : (const float*)g_bufB;

    __shared__ __align__(16) float Ah[128][20];
    __shared__ __align__(16) float Al[128][20];
    __shared__ __align__(16) float WhS[16][132];  // [k][g*16+j] fragment-major
    __shared__ __align__(16) float WlS[16][132];

    const int tid  = threadIdx.x;
    const int lane = tid & 31;
    const int warp = tid >> 5;
    const int q    = lane & 3;
    const int g    = lane >> 2;
    const int wrow = warp * 16;
    const int row0 = blockIdx.x * 128;

    float d[16][4];
#pragma unroll
    for (int j = 0; j < 16; j++)
#pragma unroll
        for (int i = 0; i < 4; i++) d[j][i] = 0.f;

    const int a_row = tid >> 1;
    const int a_cb  = (tid & 1) * 8;
    const int w_r   = tid >> 4;
    const int w_cb  = (tid & 15) * 8;
    const int w_j0  = w_cb >> 3;

    const int gr   = row0 + a_row;
    const bool gok = (gr < M);
    const int nkt  = K >> 4;

    float4 av0 = make_float4(0.f, 0.f, 0.f, 0.f), av1 = av0;
    if (gok) {
        av0 = *(const float4*)&A[(size_t)gr * K + a_cb];
        av1 = *(const float4*)&A[(size_t)gr * K + a_cb + 4];
    }
    float4 wv0 = *(const float4*)&W[(size_t)w_r * 128 + w_cb];
    float4 wv1 = *(const float4*)&W[(size_t)w_r * 128 + w_cb + 4];

    for (int kt = 0; kt < nkt; kt++) {
        float4 h0, l0, h1, l1;
        split4(av0, h0, l0); split4(av1, h1, l1);
        *(float4*)&Ah[a_row][a_cb]     = h0;  *(float4*)&Al[a_row][a_cb]     = l0;
        *(float4*)&Ah[a_row][a_cb + 4] = h1;  *(float4*)&Al[a_row][a_cb + 4] = l1;
        split4(wv0, h0, l0); split4(wv1, h1, l1);
        {
            float* dh = &WhS[w_r][w_j0];
            float* dl = &WlS[w_r][w_j0];
            dh[0*16] = h0.x; dh[1*16] = h0.y; dh[2*16] = h0.z; dh[3*16] = h0.w;
            dh[4*16] = h1.x; dh[5*16] = h1.y; dh[6*16] = h1.z; dh[7*16] = h1.w;
            dl[0*16] = l0.x; dl[1*16] = l0.y; dl[2*16] = l0.z; dl[3*16] = l0.w;
            dl[4*16] = l1.x; dl[5*16] = l1.y; dl[6*16] = l1.z; dl[7*16] = l1.w;
        }
        __syncthreads();

        if (kt + 1 < nkt) {
            int k0g = (kt + 1) << 4;
            av0 = make_float4(0.f, 0.f, 0.f, 0.f); av1 = av0;
            if (gok) {
                av0 = *(const float4*)&A[(size_t)gr * K + k0g + a_cb];
                av1 = *(const float4*)&A[(size_t)gr * K + k0g + a_cb + 4];
            }
            wv0 = *(const float4*)&W[(size_t)(k0g + w_r) * 128 + w_cb];
            wv1 = *(const float4*)&W[(size_t)(k0g + w_r) * 128 + w_cb + 4];
        }

#pragma unroll
        for (int ks = 0; ks < 2; ks++) {
            const int k0 = ks * 8;
            unsigned ah0 = __float_as_uint(Ah[wrow + g][k0 + q]);
            unsigned ah1 = __float_as_uint(Ah[wrow + g + 8][k0 + q]);
            unsigned ah2 = __float_as_uint(Ah[wrow + g][k0 + q + 4]);
            unsigned ah3 = __float_as_uint(Ah[wrow + g + 8][k0 + q + 4]);
            unsigned al0 = __float_as_uint(Al[wrow + g][k0 + q]);
            unsigned al1 = __float_as_uint(Al[wrow + g + 8][k0 + q]);
            unsigned al2 = __float_as_uint(Al[wrow + g][k0 + q + 4]);
            unsigned al3 = __float_as_uint(Al[wrow + g + 8][k0 + q + 4]);
            const float* WhR0 = &WhS[k0 + q][g * 16];
            const float* WhR1 = &WhS[k0 + q + 4][g * 16];
            const float* WlR0 = &WlS[k0 + q][g * 16];
            const float* WlR1 = &WlS[k0 + q + 4][g * 16];
#pragma unroll
            for (int c = 0; c < 4; c++) {
                float4 vh0 = *(const float4*)&WhR0[4 * c];
                float4 vh1 = *(const float4*)&WhR1[4 * c];
                float4 vl0 = *(const float4*)&WlR0[4 * c];
                float4 vl1 = *(const float4*)&WlR1[4 * c];
                const float* ph0 = (const float*)&vh0;
                const float* ph1 = (const float*)&vh1;
                const float* pl0 = (const float*)&vl0;
                const float* pl1 = (const float*)&vl1;
#pragma unroll
                for (int e = 0; e < 4; e++) {
                    const int j = c * 4 + e;
                    unsigned bh0 = __float_as_uint(ph0[e]);
                    unsigned bh1 = __float_as_uint(ph1[e]);
                    unsigned bl0 = __float_as_uint(pl0[e]);
                    unsigned bl1 = __float_as_uint(pl1[e]);
                    mma8(d[j], ah0, ah1, ah2, ah3, bh0, bh1);
                    mma8(d[j], al0, al1, al2, al3, bh0, bh1);
                    mma8(d[j], ah0, ah1, ah2, ah3, bl0, bl1);
                }
            }
        }
        __syncthreads();
    }

    const int r0 = row0 + wrow + g;
    const int r1 = r0 + 8;

    // write h as fp16 (fp32 C is dead — only the gather reads h)
#pragma unroll
    for (int j = 0; j < 16; j++) {
        int col = j * 8 + 2 * q;
        if (r0 < M) *(__half2*)&g_bufH[(size_t)r0 * 128 + col] = __floats2half2_rn(d[j][0], d[j][1]);
        if (r1 < M) *(__half2*)&g_bufH[(size_t)r1 * 128 + col] = __floats2half2_rn(d[j][2], d[j][3]);
    }

    // fused attention logits (from fp32 accumulators)
#pragma unroll
    for (int hd = 0; hd < 8; hd++) {
        float ss0 = 0.f, ds0 = 0.f, ss1 = 0.f, ds1 = 0.f;
#pragma unroll
        for (int jj = 0; jj < 2; jj++) {
            int j = hd * 2 + jj;
            int c = jj * 8 + 2 * q;
            float as0 = a_src[hd * CH + c], as1 = a_src[hd * CH + c + 1];
            float ad0 = a_dst[hd * CH + c], ad1 = a_dst[hd * CH + c + 1];
            ss0 += d[j][0] * as0 + d[j][1] * as1;
            ds0 += d[j][0] * ad0 + d[j][1] * ad1;
            ss1 += d[j][2] * as0 + d[j][3] * as1;
            ds1 += d[j][2] * ad0 + d[j][3] * ad1;
        }
        ss0 += __shfl_xor_sync(0xffffffffu, ss0, 1);
        ss0 += __shfl_xor_sync(0xffffffffu, ss0, 2);
        ds0 += __shfl_xor_sync(0xffffffffu, ds0, 1);
        ds0 += __shfl_xor_sync(0xffffffffu, ds0, 2);
        ss1 += __shfl_xor_sync(0xffffffffu, ss1, 1);
        ss1 += __shfl_xor_sync(0xffffffffu, ss1, 2);
        ds1 += __shfl_xor_sync(0xffffffffu, ds1, 1);
        ds1 += __shfl_xor_sync(0xffffffffu, ds1, 2);
        if (q == 0) {
            if (r0 < M) { g_alsrc[r0 * 8 + hd] = ss0; g_aldst[r0 * 8 + hd] = ds0; }
            if (r1 < M) { g_alsrc[r1 * 8 + hd] = ss1; g_aldst[r1 * 8 + hd] = ds1; }
        }
    }
}

// ---------------- per-node softmax + aggregation (one warp / node, fp16 gather) ----
__device__ __forceinline__ void hload4(int s, int lane, float4& v) {
    uint2 raw = *(const uint2*)&g_bufH[(size_t)s * FEAT + lane * 4];
    float2 f0 = __half22float2(*(__half2*)&raw.x);
    float2 f1 = __half22float2(*(__half2*)&raw.y);
    v.x = f0.x; v.y = f0.y; v.z = f1.x; v.w = f1.y;
}

template <int MODE>
__global__ void k_agg(const float* __restrict__ bias, float* __restrict__ outp,
                      const float* __restrict__ an_w1, const float* __restrict__ an_b1,
                      const float* __restrict__ an_w2, const float* __restrict__ an_b2) {
    int gw = (blockIdx.x * blockDim.x + threadIdx.x) >> 5;
    if (gw >= N_NODES) return;
    int lane = threadIdx.x & 31;
    int d = gw;
    float* __restrict__ out = (MODE == 0) ? (float*)g_bufB : outp;
    int beg = g_rowptr[d], end = g_rowptr[d + 1];

    float adst = 0.f, asrc_self = 0.f;
    if (lane < 8) {
        adst      = g_aldst[d * 8 + lane];
        asrc_self = g_alsrc[d * 8 + lane];
    }
    const int head = lane >> 2;
    float den = 0.f;
    float4 acc = make_float4(0.f, 0.f, 0.f, 0.f);

    int i = beg;
    int sA = (i < end) ? g_col[i] : -1;
    float alA = 0.f;
    float4 hA = make_float4(0.f, 0.f, 0.f, 0.f);
    if (sA >= 0) {
        if (lane < 8) alA = g_alsrc[sA * 8 + lane];
        hload4(sA, lane, hA);
    }
    {   // self loop
        float p = 0.f;
        if (lane < 8) { p = __expf(lrelu02(asrc_self + adst)); den += p; }
        float w = __shfl_sync(0xffffffffu, p, head);
        float4 hv; hload4(d, lane, hv);
        acc.x += hv.x * w; acc.y += hv.y * w; acc.z += hv.z * w; acc.w += hv.w * w;
    }
    while (sA >= 0) {
        int ii = i + 1;
        int sB = (ii < end) ? g_col[ii] : -1;
        float alB = 0.f;
        float4 hB = make_float4(0.f, 0.f, 0.f, 0.f);
        if (sB >= 0) {
            if (lane < 8) alB = g_alsrc[sB * 8 + lane];
            hload4(sB, lane, hB);
        }
        float p = 0.f;
        if (lane < 8) { p = __expf(lrelu02(alA + adst)); den += p; }
        float w = __shfl_sync(0xffffffffu, p, head);
        acc.x += hA.x * w; acc.y += hA.y * w; acc.z += hA.z * w; acc.w += hA.w * w;
        sA = sB; alA = alB; hA = hB; i = ii;
    }
    float denw = __shfl_sync(0xffffffffu, den, head);
    float inv = 1.f / denw;
    acc.x *= inv; acc.y *= inv; acc.z *= inv; acc.w *= inv;

    if (MODE == 0) {
        float4 bb = *(const float4*)&bias[lane * 4];
        acc.x = elu1(acc.x + bb.x);
        acc.y = elu1(acc.y + bb.y);
        acc.z = elu1(acc.z + bb.z);
        acc.w = elu1(acc.w + bb.w);
        *(float4*)&out[(size_t)d * FEAT + lane * 4] = acc;
    } else {
#pragma unroll
        for (int off = 4; off <= 16; off <<= 1) {
            acc.x += __shfl_xor_sync(0xffffffffu, acc.x, off);
            acc.y += __shfl_xor_sync(0xffffffffu, acc.y, off);
            acc.z += __shfl_xor_sync(0xffffffffu, acc.z, off);
            acc.w += __shfl_xor_sync(0xffffffffu, acc.w, off);
        }
        float4 bb = *(const float4*)&bias[(lane & 3) * 4];
        float4 r;
        r.x = acc.x * 0.125f + bb.x;
        r.y = acc.y * 0.125f + bb.y;
        r.z = acc.z * 0.125f + bb.z;
        r.w = acc.w * 0.125f + bb.w;
        if (lane < 4) *(float4*)&out[(size_t)d * CH + lane * 4] = r;

        // fused anomaly head: 16 -> 32 relu -> 1 sigmoid
        float hv[16];
#pragma unroll
        for (int c = 0; c < 16; c++) {
            float comp = ((c & 3) == 0) ? r.x : ((c & 3) == 1) ? r.y
                        : ((c & 3) == 2) ? r.z : r.w;
            hv[c] = __shfl_sync(0xffffffffu, comp, c >> 2);
        }
        float t = an_b1[lane];
#pragma unroll
        for (int c = 0; c < 16; c++) t += hv[c] * an_w1[c * 32 + lane];
        float contrib = fmaxf(t, 0.f) * an_w2[lane];
#pragma unroll
        for (int off = 16; off >= 1; off >>= 1)
            contrib += __shfl_xor_sync(0xffffffffu, contrib, off);
        if (lane == 0)
            out[800000 + d] = 1.f / (1.f + __expf(-(contrib + an_b2[0])));
    }
}

// ---------------- graph mean ----------------
__global__ void k_gsum(const float* __restrict__ hout) {
    __shared__ float sh[256];
    int tid = threadIdx.x;
    float s = 0.f;
    size_t total = (size_t)N_NODES * 16;
    size_t stride = (size_t)gridDim.x * 256;
    for (size_t idx = (size_t)blockIdx.x * 256 + tid; idx < total; idx += stride)
        s += hout[idx];
    sh[tid] = s;
    __syncthreads();
    for (int off = 128; off >= 16; off >>= 1) {
        if (tid < off) sh[tid] += sh[tid + off];
        __syncthreads();
    }
    if (tid < 16) atomicAdd(&g_gsum[tid], sh[tid]);
}

// ---------------- graph classifier ----------------
__global__ void k_final(const float* __restrict__ w1, const float* __restrict__ b1,
                        const float* __restrict__ w2, const float* __restrict__ b2,
                        float* __restrict__ out) {
    __shared__ float emb[16];
    __shared__ float hid[64];
    int t = threadIdx.x;
    if (t < 16) {
        float e = g_gsum[t] * (1.f / (float)N_NODES);
        emb[t] = e;
        out[850000 + t] = e;
    }
    __syncthreads();
    float s = b1[t];
#pragma unroll
    for (int c = 0; c < 16; c++) s += emb[c] * w1[c * 64 + t];
    hid[t] = fmaxf(s, 0.f);
    __syncthreads();
    if (t < 2) {
        float r = b2[t];
#pragma unroll
        for (int u = 0; u < 64; u++) r += hid[u] * w2[u * 2 + t];
        out[850016 + t] = r;
    }
}

// ---------------- launch ----------------
extern "C" void kernel_launch(void* const* d_in, const int* in_sizes, int n_in,
                              void* d_out, int out_size) {
    const float* x      = (const float*)d_in[0];
    const void*  ei     = d_in[1];
    const float* W1     = (const float*)d_in[2];
    const float* a1s    = (const float*)d_in[3];
    const float* a1d    = (const float*)d_in[4];
    const float* b1     = (const float*)d_in[5];
    const float* W2     = (const float*)d_in[6];
    const float* a2s    = (const float*)d_in[7];
    const float* a2d    = (const float*)d_in[8];
    const float* b2     = (const float*)d_in[9];
    const float* W3     = (const float*)d_in[10];
    const float* a3s    = (const float*)d_in[11];
    const float* a3d    = (const float*)d_in[12];
    const float* b3     = (const float*)d_in[13];
    const float* cls_w1 = (const float*)d_in[14];
    const float* cls_b1 = (const float*)d_in[15];
    const float* cls_w2 = (const float*)d_in[16];
    const float* cls_b2 = (const float*)d_in[17];
    const float* an_w1  = (const float*)d_in[18];
    const float* an_b1  = (const float*)d_in[19];
    const float* an_w2  = (const float*)d_in[20];
    const float* an_b2  = (const float*)d_in[21];
    float* out = (float*)d_out;

    const int TB = 256;
    const int nodeBlocks = (N_NODES + TB - 1) / TB;
    const int edgeBlocks = (N_EDGES + TB - 1) / TB;
    const int aggBlocks  = (N_NODES * 32 + TB - 1) / TB;
    const int gemmBlocks = (N_NODES + 127) / 128;  // 391
    const int nchunks    = (N_NODES + 1023) / 1024;

    // layer-1 GEMM kept in the profiled slot (4th launch)
    k_detect<<<1, 1024>>>((const unsigned int*)ei);
    k_zero<<<nodeBlocks, TB>>>();
    k_count<<<edgeBlocks, TB>>>(ei);
    k_gemm<0><<<gemmBlocks, TB>>>(x, W1, a1s, a1d, N_NODES, 256);   // profiled
    k_scan1<<<nchunks, 1024>>>();
    k_scan2<<<1, 32>>>(nchunks);
    k_scan3<<<nodeBlocks, TB>>>();
    k_scatter<<<edgeBlocks, TB>>>(ei);

    k_agg<0><<<aggBlocks, TB>>>(b1, nullptr, nullptr, nullptr, nullptr, nullptr);

    k_gemm<1><<<gemmBlocks, TB>>>(nullptr, W2, a2s, a2d, N_NODES, 128);
    k_agg<0><<<aggBlocks, TB>>>(b2, nullptr, nullptr, nullptr, nullptr, nullptr);

    k_gemm<1><<<gemmBlocks, TB>>>(nullptr, W3, a3s, a3d, N_NODES, 128);
    k_agg<1><<<aggBlocks, TB>>>(b3, out, an_w1, an_b1, an_w2, an_b2);

    k_gsum<<<64, TB>>>(out);
    k_final<<<1, 64>>>(cls_w1, cls_b1, cls_w2, cls_b2, out);
}

// round 11
// speedup vs baseline: 1.2857x; 1.2525x over previous
#include <cuda_runtime.h>
#include <cuda_bf16.h>
#include <math.h>

#define N_NODES 50000
#define N_EDGES 800000
#define FEAT    128
#define HEADS   8
#define CH      16

// ---------------- scratch (no allocs; referenced ONLY from device code) ----------
static __device__ __align__(16) float g_bufA[(size_t)N_NODES * FEAT];  // h (fp32)
static __device__ __align__(16) float g_bufB[(size_t)N_NODES * FEAT];  // agg out
static __device__ float g_alsrc[N_NODES * HEADS];
static __device__ float g_aldst[N_NODES * HEADS];
static __device__ int   g_rowptr[N_NODES + 1];
static __device__ int   g_cnt[N_NODES];
static __device__ int   g_fill[N_NODES];
static __device__ int   g_col[N_EDGES];
static __device__ int   g_incl[N_NODES];
static __device__ int   g_bsum[64];
static __device__ float g_gsum[16];
static __device__ int   g_is64;

__device__ __forceinline__ float lrelu02(float x) { return x > 0.f ? x : 0.2f * x; }
__device__ __forceinline__ float elu1(float x)    { return x > 0.f ? x : (__expf(x) - 1.f); }
__device__ __forceinline__ int   clampN(int v)    { return v < 0 ? 0 : (v >= N_NODES ? N_NODES - 1 : v); }

// ---------------- edge dtype probe ----------------
__global__ void k_detect(const unsigned int* __restrict__ w) {
    __shared__ unsigned int sh[1024];
    int t = threadIdx.x;
    sh[t] = w[2 * t + 1];
    __syncthreads();
    for (int off = 512; off > 0; off >>= 1) {
        if (t < off) sh[t] |= sh[t + off];
        __syncthreads();
    }
    if (t == 0) g_is64 = (sh[0] == 0u) ? 1 : 0;
}

__device__ __forceinline__ int load_src(const void* eiv, int e) {
    return clampN(g_is64 ? (int)((const long long*)eiv)[e] : ((const int*)eiv)[e]);
}
__device__ __forceinline__ int load_dst(const void* eiv, int e) {
    return clampN(g_is64 ? (int)((const long long*)eiv)[N_EDGES + e]
                         : ((const int*)eiv)[N_EDGES + e]);
}

// ---------------- CSR build ----------------
__global__ void k_zero() {
    int i = blockIdx.x * blockDim.x + threadIdx.x;
    if (i < N_NODES) { g_cnt[i] = 0; g_fill[i] = 0; }
    if (i < 16) g_gsum[i] = 0.f;
}

__global__ void k_count(const void* __restrict__ eiv) {
    int e = blockIdx.x * blockDim.x + threadIdx.x;
    if (e >= N_EDGES) return;
    atomicAdd(&g_cnt[load_dst(eiv, e)], 1);
}

__global__ void k_scan1() {
    __shared__ int sh[1024];
    int t = threadIdx.x;
    int g = blockIdx.x * 1024 + t;
    int v = (g < N_NODES) ? g_cnt[g] : 0;
    sh[t] = v;
    __syncthreads();
    for (int off = 1; off < 1024; off <<= 1) {
        int add = (t >= off) ? sh[t - off] : 0;
        __syncthreads();
        sh[t] += add;
        __syncthreads();
    }
    if (g < N_NODES) g_incl[g] = sh[t];
    if (t == 1023) g_bsum[blockIdx.x] = sh[1023];
}

__global__ void k_scan2(int nchunks) {
    if (threadIdx.x == 0) {
        int acc = 0;
        for (int i = 0; i < nchunks; i++) { int v = g_bsum[i]; g_bsum[i] = acc; acc += v; }
    }
}

__global__ void k_scan3() {
    int i = blockIdx.x * blockDim.x + threadIdx.x;
    if (i >= N_NODES) return;
    g_rowptr[i + 1] = g_incl[i] + g_bsum[i >> 10];
    if (i == 0) g_rowptr[0] = 0;
}

__global__ void k_scatter(const void* __restrict__ eiv) {
    int e = blockIdx.x * blockDim.x + threadIdx.x;
    if (e >= N_EDGES) return;
    int d = load_dst(eiv, e);
    int pos = g_rowptr[d] + atomicAdd(&g_fill[d], 1);
    g_col[pos] = load_src(eiv, e);
}

// ---------------- tf32 helpers ----------------
__device__ __forceinline__ void split4(float4 v, float4& hi, float4& lo) {
    hi.x = __uint_as_float(__float_as_uint(v.x) & 0xffffe000u); lo.x = v.x - hi.x;
    hi.y = __uint_as_float(__float_as_uint(v.y) & 0xffffe000u); lo.y = v.y - hi.y;
    hi.z = __uint_as_float(__float_as_uint(v.z) & 0xffffe000u); lo.z = v.z - hi.z;
    hi.w = __uint_as_float(__float_as_uint(v.w) & 0xffffe000u); lo.w = v.w - hi.w;
}

__device__ __forceinline__ void mma8(float* d,
                                     unsigned a0, unsigned a1, unsigned a2, unsigned a3,
                                     unsigned b0, unsigned b1) {
    asm volatile(
        "mma.sync.aligned.m16n8k8.row.col.f32.tf32.tf32.f32 "
        "{%0,%1,%2,%3}, {%4,%5,%6,%7}, {%8,%9}, {%0,%1,%2,%3};\n"
        : "+f"(d[0]), "+f"(d[1]), "+f"(d[2]), "+f"(d[3])
        : "r"(a0), "r"(a1), "r"(a2), "r"(a3), "r"(b0), "r"(b1));
}

// ---------------- tensor-core GEMM (3xTF32, round-8 config) ----------------
// g_bufA[M,128] = A[M,K] @ W[K,128]; fused logits to g_alsrc/g_aldst.
template <int SRC>
__global__ __launch_bounds__(256, 2) void k_gemm(const float* __restrict__ Ain,
                                                 const float* __restrict__ W,
                                                 const float* __restrict__ a_src,
                                                 const float* __restrict__ a_dst,
                                                 int M, int K) {
    const float* __restrict__ A = (SRC == 0) ? Ain : (const float*)g_bufB;
    float* __restrict__ C = g_bufA;

    __shared__ __align__(16) float Ah[128][20];
    __shared__ __align__(16) float Al[128][20];
    __shared__ __align__(16) float WhS[16][132];  // [k][g*16+j] fragment-major
    __shared__ __align__(16) float WlS[16][132];

    const int tid  = threadIdx.x;
    const int lane = tid & 31;
    const int warp = tid >> 5;
    const int q    = lane & 3;
    const int g    = lane >> 2;
    const int wrow = warp * 16;
    const int row0 = blockIdx.x * 128;

    float d[16][4];
#pragma unroll
    for (int j = 0; j < 16; j++)
#pragma unroll
        for (int i = 0; i < 4; i++) d[j][i] = 0.f;

    const int a_row = tid >> 1;
    const int a_cb  = (tid & 1) * 8;
    const int w_r   = tid >> 4;
    const int w_cb  = (tid & 15) * 8;
    const int w_j0  = w_cb >> 3;

    const int gr   = row0 + a_row;
    const bool gok = (gr < M);
    const int nkt  = K >> 4;

    float4 av0 = make_float4(0.f, 0.f, 0.f, 0.f), av1 = av0;
    if (gok) {
        av0 = *(const float4*)&A[(size_t)gr * K + a_cb];
        av1 = *(const float4*)&A[(size_t)gr * K + a_cb + 4];
    }
    float4 wv0 = *(const float4*)&W[(size_t)w_r * 128 + w_cb];
    float4 wv1 = *(const float4*)&W[(size_t)w_r * 128 + w_cb + 4];

    for (int kt = 0; kt < nkt; kt++) {
        float4 h0, l0, h1, l1;
        split4(av0, h0, l0); split4(av1, h1, l1);
        *(float4*)&Ah[a_row][a_cb]     = h0;  *(float4*)&Al[a_row][a_cb]     = l0;
        *(float4*)&Ah[a_row][a_cb + 4] = h1;  *(float4*)&Al[a_row][a_cb + 4] = l1;
        split4(wv0, h0, l0); split4(wv1, h1, l1);
        {
            float* dh = &WhS[w_r][w_j0];
            float* dl = &WlS[w_r][w_j0];
            dh[0*16] = h0.x; dh[1*16] = h0.y; dh[2*16] = h0.z; dh[3*16] = h0.w;
            dh[4*16] = h1.x; dh[5*16] = h1.y; dh[6*16] = h1.z; dh[7*16] = h1.w;
            dl[0*16] = l0.x; dl[1*16] = l0.y; dl[2*16] = l0.z; dl[3*16] = l0.w;
            dl[4*16] = l1.x; dl[5*16] = l1.y; dl[6*16] = l1.z; dl[7*16] = l1.w;
        }
        __syncthreads();

        if (kt + 1 < nkt) {
            int k0g = (kt + 1) << 4;
            av0 = make_float4(0.f, 0.f, 0.f, 0.f); av1 = av0;
            if (gok) {
                av0 = *(const float4*)&A[(size_t)gr * K + k0g + a_cb];
                av1 = *(const float4*)&A[(size_t)gr * K + k0g + a_cb + 4];
            }
            wv0 = *(const float4*)&W[(size_t)(k0g + w_r) * 128 + w_cb];
            wv1 = *(const float4*)&W[(size_t)(k0g + w_r) * 128 + w_cb + 4];
        }

#pragma unroll
        for (int ks = 0; ks < 2; ks++) {
            const int k0 = ks * 8;
            unsigned ah0 = __float_as_uint(Ah[wrow + g][k0 + q]);
            unsigned ah1 = __float_as_uint(Ah[wrow + g + 8][k0 + q]);
            unsigned ah2 = __float_as_uint(Ah[wrow + g][k0 + q + 4]);
            unsigned ah3 = __float_as_uint(Ah[wrow + g + 8][k0 + q + 4]);
            unsigned al0 = __float_as_uint(Al[wrow + g][k0 + q]);
            unsigned al1 = __float_as_uint(Al[wrow + g + 8][k0 + q]);
            unsigned al2 = __float_as_uint(Al[wrow + g][k0 + q + 4]);
            unsigned al3 = __float_as_uint(Al[wrow + g + 8][k0 + q + 4]);
            const float* WhR0 = &WhS[k0 + q][g * 16];
            const float* WhR1 = &WhS[k0 + q + 4][g * 16];
            const float* WlR0 = &WlS[k0 + q][g * 16];
            const float* WlR1 = &WlS[k0 + q + 4][g * 16];
#pragma unroll
            for (int c = 0; c < 4; c++) {
                float4 vh0 = *(const float4*)&WhR0[4 * c];
                float4 vh1 = *(const float4*)&WhR1[4 * c];
                float4 vl0 = *(const float4*)&WlR0[4 * c];
                float4 vl1 = *(const float4*)&WlR1[4 * c];
                const float* ph0 = (const float*)&vh0;
                const float* ph1 = (const float*)&vh1;
                const float* pl0 = (const float*)&vl0;
                const float* pl1 = (const float*)&vl1;
#pragma unroll
                for (int e = 0; e < 4; e++) {
                    const int j = c * 4 + e;
                    unsigned bh0 = __float_as_uint(ph0[e]);
                    unsigned bh1 = __float_as_uint(ph1[e]);
                    unsigned bl0 = __float_as_uint(pl0[e]);
                    unsigned bl1 = __float_as_uint(pl1[e]);
                    mma8(d[j], ah0, ah1, ah2, ah3, bh0, bh1);
                    mma8(d[j], al0, al1, al2, al3, bh0, bh1);
                    mma8(d[j], ah0, ah1, ah2, ah3, bl0, bl1);
                }
            }
        }
        __syncthreads();
    }

    const int r0 = row0 + wrow + g;
    const int r1 = r0 + 8;

#pragma unroll
    for (int j = 0; j < 16; j++) {
        int col = j * 8 + 2 * q;
        if (r0 < M) *(float2*)&C[(size_t)r0 * 128 + col] = make_float2(d[j][0], d[j][1]);
        if (r1 < M) *(float2*)&C[(size_t)r1 * 128 + col] = make_float2(d[j][2], d[j][3]);
    }

    // fused attention logits
#pragma unroll
    for (int hd = 0; hd < 8; hd++) {
        float ss0 = 0.f, ds0 = 0.f, ss1 = 0.f, ds1 = 0.f;
#pragma unroll
        for (int jj = 0; jj < 2; jj++) {
            int j = hd * 2 + jj;
            int c = jj * 8 + 2 * q;
            float as0 = a_src[hd * CH + c], as1 = a_src[hd * CH + c + 1];
            float ad0 = a_dst[hd * CH + c], ad1 = a_dst[hd * CH + c + 1];
            ss0 += d[j][0] * as0 + d[j][1] * as1;
            ds0 += d[j][0] * ad0 + d[j][1] * ad1;
            ss1 += d[j][2] * as0 + d[j][3] * as1;
            ds1 += d[j][2] * ad0 + d[j][3] * ad1;
        }
        ss0 += __shfl_xor_sync(0xffffffffu, ss0, 1);
        ss0 += __shfl_xor_sync(0xffffffffu, ss0, 2);
        ds0 += __shfl_xor_sync(0xffffffffu, ds0, 1);
        ds0 += __shfl_xor_sync(0xffffffffu, ds0, 2);
        ss1 += __shfl_xor_sync(0xffffffffu, ss1, 1);
        ss1 += __shfl_xor_sync(0xffffffffu, ss1, 2);
        ds1 += __shfl_xor_sync(0xffffffffu, ds1, 1);
        ds1 += __shfl_xor_sync(0xffffffffu, ds1, 2);
        if (q == 0) {
            if (r0 < M) { g_alsrc[r0 * 8 + hd] = ss0; g_aldst[r0 * 8 + hd] = ds0; }
            if (r1 < M) { g_alsrc[r1 * 8 + hd] = ss1; g_aldst[r1 * 8 + hd] = ds1; }
        }
    }
}

// ---------------- per-node softmax + aggregation (one warp / node) ----------------
// Lean loop: every lane loads its head's logit (quad-broadcast) and computes its
// own exp — no predication, no shfl in the loop, no pipeline moves. Unroll x4.
template <int MODE>
__global__ void k_agg(const float* __restrict__ bias, float* __restrict__ outp,
                      const float* __restrict__ an_w1, const float* __restrict__ an_b1,
                      const float* __restrict__ an_w2, const float* __restrict__ an_b2) {
    int gw = (blockIdx.x * blockDim.x + threadIdx.x) >> 5;
    if (gw >= N_NODES) return;
    int lane = threadIdx.x & 31;
    int d = gw;
    const float* __restrict__ h = g_bufA;
    float* __restrict__ out = (MODE == 0) ? (float*)g_bufB : outp;
    const int beg = g_rowptr[d], end = g_rowptr[d + 1];
    const int head = lane >> 2;

    const float adst = g_aldst[d * 8 + head];   // quad-broadcast
    float den;
    float4 acc;
    {   // self loop
        float p = __expf(lrelu02(g_alsrc[d * 8 + head] + adst));
        den = p;
        float4 hv = *(const float4*)&h[(size_t)d * FEAT + lane * 4];
        acc.x = hv.x * p; acc.y = hv.y * p; acc.z = hv.z * p; acc.w = hv.w * p;
    }
    int i = beg;
    for (; i + 4 <= end; i += 4) {
        int s0 = g_col[i], s1 = g_col[i + 1], s2 = g_col[i + 2], s3 = g_col[i + 3];
        float a0 = g_alsrc[s0 * 8 + head];
        float a1 = g_alsrc[s1 * 8 + head];
        float a2 = g_alsrc[s2 * 8 + head];
        float a3 = g_alsrc[s3 * 8 + head];
        float4 h0 = *(const float4*)&h[(size_t)s0 * FEAT + lane * 4];
        float4 h1 = *(const float4*)&h[(size_t)s1 * FEAT + lane * 4];
        float4 h2 = *(const float4*)&h[(size_t)s2 * FEAT + lane * 4];
        float4 h3 = *(const float4*)&h[(size_t)s3 * FEAT + lane * 4];
        float p0 = __expf(lrelu02(a0 + adst));
        float p1 = __expf(lrelu02(a1 + adst));
        float p2 = __expf(lrelu02(a2 + adst));
        float p3 = __expf(lrelu02(a3 + adst));
        den += (p0 + p1) + (p2 + p3);
        acc.x += h0.x * p0 + h1.x * p1 + h2.x * p2 + h3.x * p3;
        acc.y += h0.y * p0 + h1.y * p1 + h2.y * p2 + h3.y * p3;
        acc.z += h0.z * p0 + h1.z * p1 + h2.z * p2 + h3.z * p3;
        acc.w += h0.w * p0 + h1.w * p1 + h2.w * p2 + h3.w * p3;
    }
    for (; i < end; i++) {
        int s = g_col[i];
        float p = __expf(lrelu02(g_alsrc[s * 8 + head] + adst));
        den += p;
        float4 hv = *(const float4*)&h[(size_t)s * FEAT + lane * 4];
        acc.x += hv.x * p; acc.y += hv.y * p; acc.z += hv.z * p; acc.w += hv.w * p;
    }
    float inv = 1.f / den;   // each lane already holds its head's denominator
    acc.x *= inv; acc.y *= inv; acc.z *= inv; acc.w *= inv;

    if (MODE == 0) {
        float4 bb = *(const float4*)&bias[lane * 4];
        acc.x = elu1(acc.x + bb.x);
        acc.y = elu1(acc.y + bb.y);
        acc.z = elu1(acc.z + bb.z);
        acc.w = elu1(acc.w + bb.w);
        *(float4*)&out[(size_t)d * FEAT + lane * 4] = acc;
    } else {
#pragma unroll
        for (int off = 4; off <= 16; off <<= 1) {
            acc.x += __shfl_xor_sync(0xffffffffu, acc.x, off);
            acc.y += __shfl_xor_sync(0xffffffffu, acc.y, off);
            acc.z += __shfl_xor_sync(0xffffffffu, acc.z, off);
            acc.w += __shfl_xor_sync(0xffffffffu, acc.w, off);
        }
        float4 bb = *(const float4*)&bias[(lane & 3) * 4];
        float4 r;
        r.x = acc.x * 0.125f + bb.x;
        r.y = acc.y * 0.125f + bb.y;
        r.z = acc.z * 0.125f + bb.z;
        r.w = acc.w * 0.125f + bb.w;
        if (lane < 4) *(float4*)&out[(size_t)d * CH + lane * 4] = r;

        // fused anomaly head: 16 -> 32 relu -> 1 sigmoid
        float hv[16];
#pragma unroll
        for (int c = 0; c < 16; c++) {
            float comp = ((c & 3) == 0) ? r.x : ((c & 3) == 1) ? r.y
                        : ((c & 3) == 2) ? r.z : r.w;
            hv[c] = __shfl_sync(0xffffffffu, comp, c >> 2);
        }
        float t = an_b1[lane];
#pragma unroll
        for (int c = 0; c < 16; c++) t += hv[c] * an_w1[c * 32 + lane];
        float contrib = fmaxf(t, 0.f) * an_w2[lane];
#pragma unroll
        for (int off = 16; off >= 1; off >>= 1)
            contrib += __shfl_xor_sync(0xffffffffu, contrib, off);
        if (lane == 0)
            out[800000 + d] = 1.f / (1.f + __expf(-(contrib + an_b2[0])));
    }
}

// ---------------- graph mean ----------------
__global__ void k_gsum(const float* __restrict__ hout) {
    __shared__ float sh[256];
    int tid = threadIdx.x;
    float s = 0.f;
    size_t total = (size_t)N_NODES * 16;
    size_t stride = (size_t)gridDim.x * 256;
    for (size_t idx = (size_t)blockIdx.x * 256 + tid; idx < total; idx += stride)
        s += hout[idx];
    sh[tid] = s;
    __syncthreads();
    for (int off = 128; off >= 16; off >>= 1) {
        if (tid < off) sh[tid] += sh[tid + off];
        __syncthreads();
    }
    if (tid < 16) atomicAdd(&g_gsum[tid], sh[tid]);
}

// ---------------- graph classifier ----------------
__global__ void k_final(const float* __restrict__ w1, const float* __restrict__ b1,
                        const float* __restrict__ w2, const float* __restrict__ b2,
                        float* __restrict__ out) {
    __shared__ float emb[16];
    __shared__ float hid[64];
    int t = threadIdx.x;
    if (t < 16) {
        float e = g_gsum[t] * (1.f / (float)N_NODES);
        emb[t] = e;
        out[850000 + t] = e;
    }
    __syncthreads();
    float s = b1[t];
#pragma unroll
    for (int c = 0; c < 16; c++) s += emb[c] * w1[c * 64 + t];
    hid[t] = fmaxf(s, 0.f);
    __syncthreads();
    if (t < 2) {
        float r = b2[t];
#pragma unroll
        for (int u = 0; u < 64; u++) r += hid[u] * w2[u * 2 + t];
        out[850016 + t] = r;
    }
}

// ---------------- launch ----------------
extern "C" void kernel_launch(void* const* d_in, const int* in_sizes, int n_in,
                              void* d_out, int out_size) {
    const float* x      = (const float*)d_in[0];
    const void*  ei     = d_in[1];
    const float* W1     = (const float*)d_in[2];
    const float* a1s    = (const float*)d_in[3];
    const float* a1d    = (const float*)d_in[4];
    const float* b1     = (const float*)d_in[5];
    const float* W2     = (const float*)d_in[6];
    const float* a2s    = (const float*)d_in[7];
    const float* a2d    = (const float*)d_in[8];
    const float* b2     = (const float*)d_in[9];
    const float* W3     = (const float*)d_in[10];
    const float* a3s    = (const float*)d_in[11];
    const float* a3d    = (const float*)d_in[12];
    const float* b3     = (const float*)d_in[13];
    const float* cls_w1 = (const float*)d_in[14];
    const float* cls_b1 = (const float*)d_in[15];
    const float* cls_w2 = (const float*)d_in[16];
    const float* cls_b2 = (const float*)d_in[17];
    const float* an_w1  = (const float*)d_in[18];
    const float* an_b1  = (const float*)d_in[19];
    const float* an_w2  = (const float*)d_in[20];
    const float* an_b2  = (const float*)d_in[21];
    float* out = (float*)d_out;

    const int TB = 256;
    const int nodeBlocks = (N_NODES + TB - 1) / TB;
    const int edgeBlocks = (N_EDGES + TB - 1) / TB;
    const int aggBlocks  = (N_NODES * 32 + TB - 1) / TB;
    const int gemmBlocks = (N_NODES + 127) / 128;  // 391
    const int nchunks    = (N_NODES + 1023) / 1024;

    // layer-1 GEMM kept in the profiled slot (4th launch)
    k_detect<<<1, 1024>>>((const unsigned int*)ei);
    k_zero<<<nodeBlocks, TB>>>();
    k_count<<<edgeBlocks, TB>>>(ei);
    k_gemm<0><<<gemmBlocks, TB>>>(x, W1, a1s, a1d, N_NODES, 256);   // profiled
    k_scan1<<<nchunks, 1024>>>();
    k_scan2<<<1, 32>>>(nchunks);
    k_scan3<<<nodeBlocks, TB>>>();
    k_scatter<<<edgeBlocks, TB>>>(ei);

    k_agg<0><<<aggBlocks, TB>>>(b1, nullptr, nullptr, nullptr, nullptr, nullptr);

    k_gemm<1><<<gemmBlocks, TB>>>(nullptr, W2, a2s, a2d, N_NODES, 128);
    k_agg<0><<<aggBlocks, TB>>>(b2, nullptr, nullptr, nullptr, nullptr, nullptr);

    k_gemm<1><<<gemmBlocks, TB>>>(nullptr, W3, a3s, a3d, N_NODES, 128);
    k_agg<1><<<aggBlocks, TB>>>(b3, out, an_w1, an_b1, an_w2, an_b2);

    k_gsum<<<64, TB>>>(out);
    k_final<<<1, 64>>>(cls_w1, cls_b1, cls_w2, cls_b2, out);
}

// round 12
// speedup vs baseline: 1.2936x; 1.0062x over previous
#include <cuda_runtime.h>
#include <cuda_bf16.h>
#include <cuda_fp16.h>
#include <math.h>

#define N_NODES 50000
#define N_EDGES 800000
#define FEAT    128
#define HEADS   8
#define CH      16

// ---------------- scratch (no allocs; referenced ONLY from device code) ----------
static __device__ __align__(16) __half g_bufH[(size_t)N_NODES * FEAT];  // h (fp16)
static __device__ __align__(16) float  g_bufB[(size_t)N_NODES * FEAT];  // agg out (fp32)
static __device__ float g_alsrc[N_NODES * HEADS];
static __device__ float g_aldst[N_NODES * HEADS];
static __device__ int   g_rowptr[N_NODES + 1];
static __device__ int   g_cnt[N_NODES];
static __device__ int   g_fill[N_NODES];
static __device__ int   g_col[N_EDGES];
static __device__ int   g_incl[N_NODES];
static __device__ int   g_bsum[64];
static __device__ float g_gsum[16];
static __device__ int   g_is64;

__device__ __forceinline__ float lrelu02(float x) { return x > 0.f ? x : 0.2f * x; }
__device__ __forceinline__ float elu1(float x)    { return x > 0.f ? x : (__expf(x) - 1.f); }
__device__ __forceinline__ int   clampN(int v)    { return v < 0 ? 0 : (v >= N_NODES ? N_NODES - 1 : v); }

// ---------------- edge dtype probe ----------------
__global__ void k_detect(const unsigned int* __restrict__ w) {
    __shared__ unsigned int sh[1024];
    int t = threadIdx.x;
    sh[t] = w[2 * t + 1];
    __syncthreads();
    for (int off = 512; off > 0; off >>= 1) {
        if (t < off) sh[t] |= sh[t + off];
        __syncthreads();
    }
    if (t == 0) g_is64 = (sh[0] == 0u) ? 1 : 0;
}

__device__ __forceinline__ int load_src(const void* eiv, int e) {
    return clampN(g_is64 ? (int)((const long long*)eiv)[e] : ((const int*)eiv)[e]);
}
__device__ __forceinline__ int load_dst(const void* eiv, int e) {
    return clampN(g_is64 ? (int)((const long long*)eiv)[N_EDGES + e]
                         : ((const int*)eiv)[N_EDGES + e]);
}

// ---------------- CSR build ----------------
__global__ void k_zero() {
    int i = blockIdx.x * blockDim.x + threadIdx.x;
    if (i < N_NODES) { g_cnt[i] = 0; g_fill[i] = 0; }
    if (i < 16) g_gsum[i] = 0.f;
}

__global__ void k_count(const void* __restrict__ eiv) {
    int e = blockIdx.x * blockDim.x + threadIdx.x;
    if (e >= N_EDGES) return;
    atomicAdd(&g_cnt[load_dst(eiv, e)], 1);
}

__global__ void k_scan1() {
    __shared__ int sh[1024];
    int t = threadIdx.x;
    int g = blockIdx.x * 1024 + t;
    int v = (g < N_NODES) ? g_cnt[g] : 0;
    sh[t] = v;
    __syncthreads();
    for (int off = 1; off < 1024; off <<= 1) {
        int add = (t >= off) ? sh[t - off] : 0;
        __syncthreads();
        sh[t] += add;
        __syncthreads();
    }
    if (g < N_NODES) g_incl[g] = sh[t];
    if (t == 1023) g_bsum[blockIdx.x] = sh[1023];
}

__global__ void k_scan2(int nchunks) {
    if (threadIdx.x == 0) {
        int acc = 0;
        for (int i = 0; i < nchunks; i++) { int v = g_bsum[i]; g_bsum[i] = acc; acc += v; }
    }
}

__global__ void k_scan3() {
    int i = blockIdx.x * blockDim.x + threadIdx.x;
    if (i >= N_NODES) return;
    g_rowptr[i + 1] = g_incl[i] + g_bsum[i >> 10];
    if (i == 0) g_rowptr[0] = 0;
}

__global__ void k_scatter(const void* __restrict__ eiv) {
    int e = blockIdx.x * blockDim.x + threadIdx.x;
    if (e >= N_EDGES) return;
    int d = load_dst(eiv, e);
    int pos = g_rowptr[d] + atomicAdd(&g_fill[d], 1);
    g_col[pos] = load_src(eiv, e);
}

// ---------------- tf32 helpers ----------------
__device__ __forceinline__ void split4(float4 v, float4& hi, float4& lo) {
    hi.x = __uint_as_float(__float_as_uint(v.x) & 0xffffe000u); lo.x = v.x - hi.x;
    hi.y = __uint_as_float(__float_as_uint(v.y) & 0xffffe000u); lo.y = v.y - hi.y;
    hi.z = __uint_as_float(__float_as_uint(v.z) & 0xffffe000u); lo.z = v.z - hi.z;
    hi.w = __uint_as_float(__float_as_uint(v.w) & 0xffffe000u); lo.w = v.w - hi.w;
}

__device__ __forceinline__ void mma8(float* d,
                                     unsigned a0, unsigned a1, unsigned a2, unsigned a3,
                                     unsigned b0, unsigned b1) {
    asm volatile(
        "mma.sync.aligned.m16n8k8.row.col.f32.tf32.tf32.f32 "
        "{%0,%1,%2,%3}, {%4,%5,%6,%7}, {%8,%9}, {%0,%1,%2,%3};\n"
        : "+f"(d[0]), "+f"(d[1]), "+f"(d[2]), "+f"(d[3])
        : "r"(a0), "r"(a1), "r"(a2), "r"(a3), "r"(b0), "r"(b1));
}

// ---------------- tensor-core GEMM (3xTF32, round-8 config) ----------------
// h = A @ W written as fp16 to g_bufH (fp32 C is dead); logits fp32 fused.
template <int SRC>
__global__ __launch_bounds__(256, 2) void k_gemm(const float* __restrict__ Ain,
                                                 const float* __restrict__ W,
                                                 const float* __restrict__ a_src,
                                                 const float* __restrict__ a_dst,
                                                 int M, int K) {
    const float* __restrict__ A = (SRC == 0) ? Ain : (const float*)g_bufB;

    __shared__ __align__(16) float Ah[128][20];
    __shared__ __align__(16) float Al[128][20];
    __shared__ __align__(16) float WhS[16][132];  // [k][g*16+j] fragment-major
    __shared__ __align__(16) float WlS[16][132];

    const int tid  = threadIdx.x;
    const int lane = tid & 31;
    const int warp = tid >> 5;
    const int q    = lane & 3;
    const int g    = lane >> 2;
    const int wrow = warp * 16;
    const int row0 = blockIdx.x * 128;

    float d[16][4];
#pragma unroll
    for (int j = 0; j < 16; j++)
#pragma unroll
        for (int i = 0; i < 4; i++) d[j][i] = 0.f;

    const int a_row = tid >> 1;
    const int a_cb  = (tid & 1) * 8;
    const int w_r   = tid >> 4;
    const int w_cb  = (tid & 15) * 8;
    const int w_j0  = w_cb >> 3;

    const int gr   = row0 + a_row;
    const bool gok = (gr < M);
    const int nkt  = K >> 4;

    float4 av0 = make_float4(0.f, 0.f, 0.f, 0.f), av1 = av0;
    if (gok) {
        av0 = *(const float4*)&A[(size_t)gr * K + a_cb];
        av1 = *(const float4*)&A[(size_t)gr * K + a_cb + 4];
    }
    float4 wv0 = *(const float4*)&W[(size_t)w_r * 128 + w_cb];
    float4 wv1 = *(const float4*)&W[(size_t)w_r * 128 + w_cb + 4];

    for (int kt = 0; kt < nkt; kt++) {
        float4 h0, l0, h1, l1;
        split4(av0, h0, l0); split4(av1, h1, l1);
        *(float4*)&Ah[a_row][a_cb]     = h0;  *(float4*)&Al[a_row][a_cb]     = l0;
        *(float4*)&Ah[a_row][a_cb + 4] = h1;  *(float4*)&Al[a_row][a_cb + 4] = l1;
        split4(wv0, h0, l0); split4(wv1, h1, l1);
        {
            float* dh = &WhS[w_r][w_j0];
            float* dl = &WlS[w_r][w_j0];
            dh[0*16] = h0.x; dh[1*16] = h0.y; dh[2*16] = h0.z; dh[3*16] = h0.w;
            dh[4*16] = h1.x; dh[5*16] = h1.y; dh[6*16] = h1.z; dh[7*16] = h1.w;
            dl[0*16] = l0.x; dl[1*16] = l0.y; dl[2*16] = l0.z; dl[3*16] = l0.w;
            dl[4*16] = l1.x; dl[5*16] = l1.y; dl[6*16] = l1.z; dl[7*16] = l1.w;
        }
        __syncthreads();

        if (kt + 1 < nkt) {
            int k0g = (kt + 1) << 4;
            av0 = make_float4(0.f, 0.f, 0.f, 0.f); av1 = av0;
            if (gok) {
                av0 = *(const float4*)&A[(size_t)gr * K + k0g + a_cb];
                av1 = *(const float4*)&A[(size_t)gr * K + k0g + a_cb + 4];
            }
            wv0 = *(const float4*)&W[(size_t)(k0g + w_r) * 128 + w_cb];
            wv1 = *(const float4*)&W[(size_t)(k0g + w_r) * 128 + w_cb + 4];
        }

#pragma unroll
        for (int ks = 0; ks < 2; ks++) {
            const int k0 = ks * 8;
            unsigned ah0 = __float_as_uint(Ah[wrow + g][k0 + q]);
            unsigned ah1 = __float_as_uint(Ah[wrow + g + 8][k0 + q]);
            unsigned ah2 = __float_as_uint(Ah[wrow + g][k0 + q + 4]);
            unsigned ah3 = __float_as_uint(Ah[wrow + g + 8][k0 + q + 4]);
            unsigned al0 = __float_as_uint(Al[wrow + g][k0 + q]);
            unsigned al1 = __float_as_uint(Al[wrow + g + 8][k0 + q]);
            unsigned al2 = __float_as_uint(Al[wrow + g][k0 + q + 4]);
            unsigned al3 = __float_as_uint(Al[wrow + g + 8][k0 + q + 4]);
            const float* WhR0 = &WhS[k0 + q][g * 16];
            const float* WhR1 = &WhS[k0 + q + 4][g * 16];
            const float* WlR0 = &WlS[k0 + q][g * 16];
            const float* WlR1 = &WlS[k0 + q + 4][g * 16];
#pragma unroll
            for (int c = 0; c < 4; c++) {
                float4 vh0 = *(const float4*)&WhR0[4 * c];
                float4 vh1 = *(const float4*)&WhR1[4 * c];
                float4 vl0 = *(const float4*)&WlR0[4 * c];
                float4 vl1 = *(const float4*)&WlR1[4 * c];
                const float* ph0 = (const float*)&vh0;
                const float* ph1 = (const float*)&vh1;
                const float* pl0 = (const float*)&vl0;
                const float* pl1 = (const float*)&vl1;
#pragma unroll
                for (int e = 0; e < 4; e++) {
                    const int j = c * 4 + e;
                    unsigned bh0 = __float_as_uint(ph0[e]);
                    unsigned bh1 = __float_as_uint(ph1[e]);
                    unsigned bl0 = __float_as_uint(pl0[e]);
                    unsigned bl1 = __float_as_uint(pl1[e]);
                    mma8(d[j], ah0, ah1, ah2, ah3, bh0, bh1);
                    mma8(d[j], al0, al1, al2, al3, bh0, bh1);
                    mma8(d[j], ah0, ah1, ah2, ah3, bl0, bl1);
                }
            }
        }
        __syncthreads();
    }

    const int r0 = row0 + wrow + g;
    const int r1 = r0 + 8;

    // write h as fp16 (only the gather reads h)
#pragma unroll
    for (int j = 0; j < 16; j++) {
        int col = j * 8 + 2 * q;
        if (r0 < M) *(__half2*)&g_bufH[(size_t)r0 * 128 + col] = __floats2half2_rn(d[j][0], d[j][1]);
        if (r1 < M) *(__half2*)&g_bufH[(size_t)r1 * 128 + col] = __floats2half2_rn(d[j][2], d[j][3]);
    }

    // fused attention logits (fp32 accumulators)
#pragma unroll
    for (int hd = 0; hd < 8; hd++) {
        float ss0 = 0.f, ds0 = 0.f, ss1 = 0.f, ds1 = 0.f;
#pragma unroll
        for (int jj = 0; jj < 2; jj++) {
            int j = hd * 2 + jj;
            int c = jj * 8 + 2 * q;
            float as0 = a_src[hd * CH + c], as1 = a_src[hd * CH + c + 1];
            float ad0 = a_dst[hd * CH + c], ad1 = a_dst[hd * CH + c + 1];
            ss0 += d[j][0] * as0 + d[j][1] * as1;
            ds0 += d[j][0] * ad0 + d[j][1] * ad1;
            ss1 += d[j][2] * as0 + d[j][3] * as1;
            ds1 += d[j][2] * ad0 + d[j][3] * ad1;
        }
        ss0 += __shfl_xor_sync(0xffffffffu, ss0, 1);
        ss0 += __shfl_xor_sync(0xffffffffu, ss0, 2);
        ds0 += __shfl_xor_sync(0xffffffffu, ds0, 1);
        ds0 += __shfl_xor_sync(0xffffffffu, ds0, 2);
        ss1 += __shfl_xor_sync(0xffffffffu, ss1, 1);
        ss1 += __shfl_xor_sync(0xffffffffu, ss1, 2);
        ds1 += __shfl_xor_sync(0xffffffffu, ds1, 1);
        ds1 += __shfl_xor_sync(0xffffffffu, ds1, 2);
        if (q == 0) {
            if (r0 < M) { g_alsrc[r0 * 8 + hd] = ss0; g_aldst[r0 * 8 + hd] = ds0; }
            if (r1 < M) { g_alsrc[r1 * 8 + hd] = ss1; g_aldst[r1 * 8 + hd] = ds1; }
        }
    }
}

// ---------------- per-node softmax + aggregation (lean loop, fp16 gather) ----------
__device__ __forceinline__ float4 hload4(int s, int lane) {
    uint2 raw = *(const uint2*)&g_bufH[(size_t)s * FEAT + lane * 4];
    float2 f0 = __half22float2(*(__half2*)&raw.x);
    float2 f1 = __half22float2(*(__half2*)&raw.y);
    return make_float4(f0.x, f0.y, f1.x, f1.y);
}

template <int MODE>
__global__ void k_agg(const float* __restrict__ bias, float* __restrict__ outp,
                      const float* __restrict__ an_w1, const float* __restrict__ an_b1,
                      const float* __restrict__ an_w2, const float* __restrict__ an_b2) {
    int gw = (blockIdx.x * blockDim.x + threadIdx.x) >> 5;
    if (gw >= N_NODES) return;
    int lane = threadIdx.x & 31;
    int d = gw;
    float* __restrict__ out = (MODE == 0) ? (float*)g_bufB : outp;
    const int beg = g_rowptr[d], end = g_rowptr[d + 1];
    const int head = lane >> 2;

    const float adst = g_aldst[d * 8 + head];   // quad-broadcast
    float den;
    float4 acc;
    {   // self loop
        float p = __expf(lrelu02(g_alsrc[d * 8 + head] + adst));
        den = p;
        float4 hv = hload4(d, lane);
        acc.x = hv.x * p; acc.y = hv.y * p; acc.z = hv.z * p; acc.w = hv.w * p;
    }
    int i = beg;
    for (; i + 4 <= end; i += 4) {
        int s0 = g_col[i], s1 = g_col[i + 1], s2 = g_col[i + 2], s3 = g_col[i + 3];
        float a0 = g_alsrc[s0 * 8 + head];
        float a1 = g_alsrc[s1 * 8 + head];
        float a2 = g_alsrc[s2 * 8 + head];
        float a3 = g_alsrc[s3 * 8 + head];
        float4 h0 = hload4(s0, lane);
        float4 h1 = hload4(s1, lane);
        float4 h2 = hload4(s2, lane);
        float4 h3 = hload4(s3, lane);
        float p0 = __expf(lrelu02(a0 + adst));
        float p1 = __expf(lrelu02(a1 + adst));
        float p2 = __expf(lrelu02(a2 + adst));
        float p3 = __expf(lrelu02(a3 + adst));
        den += (p0 + p1) + (p2 + p3);
        acc.x += h0.x * p0 + h1.x * p1 + h2.x * p2 + h3.x * p3;
        acc.y += h0.y * p0 + h1.y * p1 + h2.y * p2 + h3.y * p3;
        acc.z += h0.z * p0 + h1.z * p1 + h2.z * p2 + h3.z * p3;
        acc.w += h0.w * p0 + h1.w * p1 + h2.w * p2 + h3.w * p3;
    }
    for (; i < end; i++) {
        int s = g_col[i];
        float p = __expf(lrelu02(g_alsrc[s * 8 + head] + adst));
        den += p;
        float4 hv = hload4(s, lane);
        acc.x += hv.x * p; acc.y += hv.y * p; acc.z += hv.z * p; acc.w += hv.w * p;
    }
    float inv = 1.f / den;
    acc.x *= inv; acc.y *= inv; acc.z *= inv; acc.w *= inv;

    if (MODE == 0) {
        float4 bb = *(const float4*)&bias[lane * 4];
        acc.x = elu1(acc.x + bb.x);
        acc.y = elu1(acc.y + bb.y);
        acc.z = elu1(acc.z + bb.z);
        acc.w = elu1(acc.w + bb.w);
        *(float4*)&out[(size_t)d * FEAT + lane * 4] = acc;
    } else {
#pragma unroll
        for (int off = 4; off <= 16; off <<= 1) {
            acc.x += __shfl_xor_sync(0xffffffffu, acc.x, off);
            acc.y += __shfl_xor_sync(0xffffffffu, acc.y, off);
            acc.z += __shfl_xor_sync(0xffffffffu, acc.z, off);
            acc.w += __shfl_xor_sync(0xffffffffu, acc.w, off);
        }
        float4 bb = *(const float4*)&bias[(lane & 3) * 4];
        float4 r;
        r.x = acc.x * 0.125f + bb.x;
        r.y = acc.y * 0.125f + bb.y;
        r.z = acc.z * 0.125f + bb.z;
        r.w = acc.w * 0.125f + bb.w;
        if (lane < 4) *(float4*)&out[(size_t)d * CH + lane * 4] = r;

        // fused anomaly head: 16 -> 32 relu -> 1 sigmoid
        float hv[16];
#pragma unroll
        for (int c = 0; c < 16; c++) {
            float comp = ((c & 3) == 0) ? r.x : ((c & 3) == 1) ? r.y
                        : ((c & 3) == 2) ? r.z : r.w;
            hv[c] = __shfl_sync(0xffffffffu, comp, c >> 2);
        }
        float t = an_b1[lane];
#pragma unroll
        for (int c = 0; c < 16; c++) t += hv[c] * an_w1[c * 32 + lane];
        float contrib = fmaxf(t, 0.f) * an_w2[lane];
#pragma unroll
        for (int off = 16; off >= 1; off >>= 1)
            contrib += __shfl_xor_sync(0xffffffffu, contrib, off);
        if (lane == 0)
            out[800000 + d] = 1.f / (1.f + __expf(-(contrib + an_b2[0])));
    }
}

// ---------------- graph mean ----------------
__global__ void k_gsum(const float* __restrict__ hout) {
    __shared__ float sh[256];
    int tid = threadIdx.x;
    float s = 0.f;
    size_t total = (size_t)N_NODES * 16;
    size_t stride = (size_t)gridDim.x * 256;
    for (size_t idx = (size_t)blockIdx.x * 256 + tid; idx < total; idx += stride)
        s += hout[idx];
    sh[tid] = s;
    __syncthreads();
    for (int off = 128; off >= 16; off >>= 1) {
        if (tid < off) sh[tid] += sh[tid + off];
        __syncthreads();
    }
    if (tid < 16) atomicAdd(&g_gsum[tid], sh[tid]);
}

// ---------------- graph classifier ----------------
__global__ void k_final(const float* __restrict__ w1, const float* __restrict__ b1,
                        const float* __restrict__ w2, const float* __restrict__ b2,
                        float* __restrict__ out) {
    __shared__ float emb[16];
    __shared__ float hid[64];
    int t = threadIdx.x;
    if (t < 16) {
        float e = g_gsum[t] * (1.f / (float)N_NODES);
        emb[t] = e;
        out[850000 + t] = e;
    }
    __syncthreads();
    float s = b1[t];
#pragma unroll
    for (int c = 0; c < 16; c++) s += emb[c] * w1[c * 64 + t];
    hid[t] = fmaxf(s, 0.f);
    __syncthreads();
    if (t < 2) {
        float r = b2[t];
#pragma unroll
        for (int u = 0; u < 64; u++) r += hid[u] * w2[u * 2 + t];
        out[850016 + t] = r;
    }
}

// ---------------- launch ----------------
extern "C" void kernel_launch(void* const* d_in, const int* in_sizes, int n_in,
                              void* d_out, int out_size) {
    const float* x      = (const float*)d_in[0];
    const void*  ei     = d_in[1];
    const float* W1     = (const float*)d_in[2];
    const float* a1s    = (const float*)d_in[3];
    const float* a1d    = (const float*)d_in[4];
    const float* b1     = (const float*)d_in[5];
    const float* W2     = (const float*)d_in[6];
    const float* a2s    = (const float*)d_in[7];
    const float* a2d    = (const float*)d_in[8];
    const float* b2     = (const float*)d_in[9];
    const float* W3     = (const float*)d_in[10];
    const float* a3s    = (const float*)d_in[11];
    const float* a3d    = (const float*)d_in[12];
    const float* b3     = (const float*)d_in[13];
    const float* cls_w1 = (const float*)d_in[14];
    const float* cls_b1 = (const float*)d_in[15];
    const float* cls_w2 = (const float*)d_in[16];
    const float* cls_b2 = (const float*)d_in[17];
    const float* an_w1  = (const float*)d_in[18];
    const float* an_b1  = (const float*)d_in[19];
    const float* an_w2  = (const float*)d_in[20];
    const float* an_b2  = (const float*)d_in[21];
    float* out = (float*)d_out;

    const int TB = 256;
    const int nodeBlocks = (N_NODES + TB - 1) / TB;
    const int edgeBlocks = (N_EDGES + TB - 1) / TB;
    const int aggBlocks  = (N_NODES * 32 + TB - 1) / TB;
    const int gemmBlocks = (N_NODES + 127) / 128;  // 391
    const int nchunks    = (N_NODES + 1023) / 1024;

    // layer-1 GEMM kept in the profiled slot (4th launch)
    k_detect<<<1, 1024>>>((const unsigned int*)ei);
    k_zero<<<nodeBlocks, TB>>>();
    k_count<<<edgeBlocks, TB>>>(ei);
    k_gemm<0><<<gemmBlocks, TB>>>(x, W1, a1s, a1d, N_NODES, 256);   // profiled
    k_scan1<<<nchunks, 1024>>>();
    k_scan2<<<1, 32>>>(nchunks);
    k_scan3<<<nodeBlocks, TB>>>();
    k_scatter<<<edgeBlocks, TB>>>(ei);

    k_agg<0><<<aggBlocks, TB>>>(b1, nullptr, nullptr, nullptr, nullptr, nullptr);

    k_gemm<1><<<gemmBlocks, TB>>>(nullptr, W2, a2s, a2d, N_NODES, 128);
    k_agg<0><<<aggBlocks, TB>>>(b2, nullptr, nullptr, nullptr, nullptr, nullptr);

    k_gemm<1><<<gemmBlocks, TB>>>(nullptr, W3, a3s, a3d, N_NODES, 128);
    k_agg<1><<<aggBlocks, TB>>>(b3, out, an_w1, an_b1, an_w2, an_b2);

    k_gsum<<<64, TB>>>(out);
    k_final<<<1, 64>>>(cls_w1, cls_b1, cls_w2, cls_b2, out);
}

// round 13
// speedup vs baseline: 1.5509x; 1.1989x over previous
#include <cuda_runtime.h>
#include <cuda_bf16.h>
#include <cuda_fp16.h>
#include <math.h>

#define N_NODES 50000
#define N_EDGES 800000
#define FEAT    128
#define HEADS   8
#define CH      16

// ---------------- scratch (no allocs; referenced ONLY from device code) ----------
static __device__ __align__(16) __half g_bufH[(size_t)N_NODES * FEAT];  // h (fp16)
static __device__ __align__(16) float  g_bufB[(size_t)N_NODES * FEAT];  // agg out (fp32)
static __device__ float g_alsrc[N_NODES * HEADS];
static __device__ float g_aldst[N_NODES * HEADS];
static __device__ int   g_rowptr[N_NODES + 1];
static __device__ int   g_cnt[N_NODES];
static __device__ int   g_fill[N_NODES];
static __device__ int   g_col[N_EDGES];
static __device__ int   g_incl[N_NODES];
static __device__ int   g_bsum[64];
static __device__ float g_gsum[16];
static __device__ int   g_is64;

__device__ __forceinline__ float lrelu02(float x) { return x > 0.f ? x : 0.2f * x; }
__device__ __forceinline__ float elu1(float x)    { return x > 0.f ? x : (__expf(x) - 1.f); }
__device__ __forceinline__ int   clampN(int v)    { return v < 0 ? 0 : (v >= N_NODES ? N_NODES - 1 : v); }

// ---------------- edge dtype probe ----------------
__global__ void k_detect(const unsigned int* __restrict__ w) {
    __shared__ unsigned int sh[1024];
    int t = threadIdx.x;
    sh[t] = w[2 * t + 1];
    __syncthreads();
    for (int off = 512; off > 0; off >>= 1) {
        if (t < off) sh[t] |= sh[t + off];
        __syncthreads();
    }
    if (t == 0) g_is64 = (sh[0] == 0u) ? 1 : 0;
}

__device__ __forceinline__ int load_src(const void* eiv, int e) {
    return clampN(g_is64 ? (int)((const long long*)eiv)[e] : ((const int*)eiv)[e]);
}
__device__ __forceinline__ int load_dst(const void* eiv, int e) {
    return clampN(g_is64 ? (int)((const long long*)eiv)[N_EDGES + e]
                         : ((const int*)eiv)[N_EDGES + e]);
}

// ---------------- CSR build ----------------
__global__ void k_zero() {
    int i = blockIdx.x * blockDim.x + threadIdx.x;
    if (i < N_NODES) { g_cnt[i] = 0; g_fill[i] = 0; }
    if (i < 16) g_gsum[i] = 0.f;
}

__global__ void k_count(const void* __restrict__ eiv) {
    int e = blockIdx.x * blockDim.x + threadIdx.x;
    if (e >= N_EDGES) return;
    atomicAdd(&g_cnt[load_dst(eiv, e)], 1);
}

__global__ void k_scan1() {
    __shared__ int sh[1024];
    int t = threadIdx.x;
    int g = blockIdx.x * 1024 + t;
    int v = (g < N_NODES) ? g_cnt[g] : 0;
    sh[t] = v;
    __syncthreads();
    for (int off = 1; off < 1024; off <<= 1) {
        int add = (t >= off) ? sh[t - off] : 0;
        __syncthreads();
        sh[t] += add;
        __syncthreads();
    }
    if (g < N_NODES) g_incl[g] = sh[t];
    if (t == 1023) g_bsum[blockIdx.x] = sh[1023];
}

__global__ void k_scan2(int nchunks) {
    if (threadIdx.x == 0) {
        int acc = 0;
        for (int i = 0; i < nchunks; i++) { int v = g_bsum[i]; g_bsum[i] = acc; acc += v; }
    }
}

__global__ void k_scan3() {
    int i = blockIdx.x * blockDim.x + threadIdx.x;
    if (i >= N_NODES) return;
    g_rowptr[i + 1] = g_incl[i] + g_bsum[i >> 10];
    if (i == 0) g_rowptr[0] = 0;
}

__global__ void k_scatter(const void* __restrict__ eiv) {
    int e = blockIdx.x * blockDim.x + threadIdx.x;
    if (e >= N_EDGES) return;
    int d = load_dst(eiv, e);
    int pos = g_rowptr[d] + atomicAdd(&g_fill[d], 1);
    g_col[pos] = load_src(eiv, e);
}

// ---------------- bf16 helpers ----------------
__device__ __forceinline__ void split_bf(float x, float& hi, float& lo) {
    __nv_bfloat16 h = __float2bfloat16(x);
    hi = __bfloat162float(h);
    lo = x - hi;
}
__device__ __forceinline__ unsigned pack_bf2(float x0, float x1) {
    __nv_bfloat162 t = __floats2bfloat162_rn(x0, x1);
    return *(unsigned*)&t;
}
__device__ __forceinline__ void mma16(float* d,
                                      unsigned a0, unsigned a1, unsigned a2, unsigned a3,
                                      unsigned b0, unsigned b1) {
    asm volatile(
        "mma.sync.aligned.m16n8k16.row.col.f32.bf16.bf16.f32 "
        "{%0,%1,%2,%3}, {%4,%5,%6,%7}, {%8,%9}, {%0,%1,%2,%3};\n"
        : "+f"(d[0]), "+f"(d[1]), "+f"(d[2]), "+f"(d[3])
        : "r"(a0), "r"(a1), "r"(a2), "r"(a3), "r"(b0), "r"(b1));
}

// ---------------- tensor-core GEMM (3xBF16 k16 split) ----------------
// h = A @ W written fp16 to g_bufH; fused logits fp32.
// BM=128, BN=128, BK=16; 8 warps, warp w owns rows w*16..w*16+15, all 128 cols.
// A smem: bf16 [128][40] (stride 20 words, conflict-free). W smem: k-pair packed
// uint32 WhP[8][132], fragment-major idx = (n&7)*16 + (n>>3).
template <int SRC>
__global__ __launch_bounds__(256, 2) void k_gemm(const float* __restrict__ Ain,
                                                 const float* __restrict__ W,
                                                 const float* __restrict__ a_src,
                                                 const float* __restrict__ a_dst,
                                                 int M, int K) {
    const float* __restrict__ A = (SRC == 0) ? Ain : (const float*)g_bufB;

    __shared__ __align__(16) __nv_bfloat16 AhS[128 * 40];
    __shared__ __align__(16) __nv_bfloat16 AlS[128 * 40];
    __shared__ __align__(16) unsigned      WhP[8 * 132];
    __shared__ __align__(16) unsigned      WlP[8 * 132];

    const int tid  = threadIdx.x;
    const int lane = tid & 31;
    const int warp = tid >> 5;
    const int q    = lane & 3;
    const int g    = lane >> 2;
    const int wrow = warp * 16;
    const int row0 = blockIdx.x * 128;

    float d[16][4];
#pragma unroll
    for (int j = 0; j < 16; j++)
#pragma unroll
        for (int i = 0; i < 4; i++) d[j][i] = 0.f;

    // staging maps: A tile 128x16 (2 float4/thread); W tile 16x128 (2 float4/thread)
    const int a_row = tid >> 1;
    const int a_kb  = (tid & 1) * 8;       // k offset 0 or 8
    const int w_k2  = tid >> 5;            // packed-k row 0..7 (covers k 2*w_k2, 2*w_k2+1)
    const int w_nb  = (lane) * 4;          // 4 n's per thread

    const int gr   = row0 + a_row;
    const bool gok = (gr < M);
    const int nkt  = K >> 4;

    // prologue prefetch (tile 0)
    float4 av0 = make_float4(0.f, 0.f, 0.f, 0.f), av1 = av0;
    if (gok) {
        av0 = *(const float4*)&A[(size_t)gr * K + a_kb];
        av1 = *(const float4*)&A[(size_t)gr * K + a_kb + 4];
    }
    float4 wv0 = *(const float4*)&W[(size_t)(2 * w_k2) * 128 + w_nb];
    float4 wv1 = *(const float4*)&W[(size_t)(2 * w_k2 + 1) * 128 + w_nb];

    for (int kt = 0; kt < nkt; kt++) {
        // ---- stage A: split 8 floats -> bf16 hi/lo, pack, 1 uint4 store each ----
        {
            float f[8] = {av0.x, av0.y, av0.z, av0.w, av1.x, av1.y, av1.z, av1.w};
            float hi[8], lo[8];
#pragma unroll
            for (int i = 0; i < 8; i++) split_bf(f[i], hi[i], lo[i]);
            uint4 vh = make_uint4(pack_bf2(hi[0], hi[1]), pack_bf2(hi[2], hi[3]),
                                  pack_bf2(hi[4], hi[5]), pack_bf2(hi[6], hi[7]));
            uint4 vl = make_uint4(pack_bf2(lo[0], lo[1]), pack_bf2(lo[2], lo[3]),
                                  pack_bf2(lo[4], lo[5]), pack_bf2(lo[6], lo[7]));
            *(uint4*)&AhS[a_row * 40 + a_kb] = vh;
            *(uint4*)&AlS[a_row * 40 + a_kb] = vl;
        }
        // ---- stage W: pack (k,k+1) pairs per n, fragment-major scatter ----
        {
            const float* p0 = (const float*)&wv0;
            const float* p1 = (const float*)&wv1;
#pragma unroll
            for (int i = 0; i < 4; i++) {
                float h0, l0, h1, l1;
                split_bf(p0[i], h0, l0);
                split_bf(p1[i], h1, l1);
                int n = w_nb + i;
                int idx = (n & 7) * 16 + (n >> 3);
                WhP[w_k2 * 132 + idx] = pack_bf2(h0, h1);
                WlP[w_k2 * 132 + idx] = pack_bf2(l0, l1);
            }
        }
        __syncthreads();

        // prefetch next tile
        if (kt + 1 < nkt) {
            int k0g = (kt + 1) << 4;
            av0 = make_float4(0.f, 0.f, 0.f, 0.f); av1 = av0;
            if (gok) {
                av0 = *(const float4*)&A[(size_t)gr * K + k0g + a_kb];
                av1 = *(const float4*)&A[(size_t)gr * K + k0g + a_kb + 4];
            }
            wv0 = *(const float4*)&W[(size_t)(k0g + 2 * w_k2) * 128 + w_nb];
            wv1 = *(const float4*)&W[(size_t)(k0g + 2 * w_k2 + 1) * 128 + w_nb];
        }

        // ---- compute: one k16 step ----
        {
            unsigned ah0 = *(const unsigned*)&AhS[(wrow + g) * 40 + 2 * q];
            unsigned ah1 = *(const unsigned*)&AhS[(wrow + g + 8) * 40 + 2 * q];
            unsigned ah2 = *(const unsigned*)&AhS[(wrow + g) * 40 + 2 * q + 8];
            unsigned ah3 = *(const unsigned*)&AhS[(wrow + g + 8) * 40 + 2 * q + 8];
            unsigned al0 = *(const unsigned*)&AlS[(wrow + g) * 40 + 2 * q];
            unsigned al1 = *(const unsigned*)&AlS[(wrow + g + 8) * 40 + 2 * q];
            unsigned al2 = *(const unsigned*)&AlS[(wrow + g) * 40 + 2 * q + 8];
            unsigned al3 = *(const unsigned*)&AlS[(wrow + g + 8) * 40 + 2 * q + 8];
#pragma unroll
            for (int c = 0; c < 4; c++) {
                uint4 vh0 = *(const uint4*)&WhP[q * 132 + g * 16 + 4 * c];
                uint4 vh1 = *(const uint4*)&WhP[(q + 4) * 132 + g * 16 + 4 * c];
                uint4 vl0 = *(const uint4*)&WlP[q * 132 + g * 16 + 4 * c];
                uint4 vl1 = *(const uint4*)&WlP[(q + 4) * 132 + g * 16 + 4 * c];
                const unsigned* b0h = (const unsigned*)&vh0;
                const unsigned* b1h = (const unsigned*)&vh1;
                const unsigned* b0l = (const unsigned*)&vl0;
                const unsigned* b1l = (const unsigned*)&vl1;
#pragma unroll
                for (int e = 0; e < 4; e++) {
                    const int j = c * 4 + e;
                    mma16(d[j], ah0, ah1, ah2, ah3, b0h[e], b1h[e]);
                    mma16(d[j], al0, al1, al2, al3, b0h[e], b1h[e]);
                    mma16(d[j], ah0, ah1, ah2, ah3, b0l[e], b1l[e]);
                }
            }
        }
        __syncthreads();
    }

    const int r0 = row0 + wrow + g;
    const int r1 = r0 + 8;

    // write h as fp16 (only the gather reads h)
#pragma unroll
    for (int j = 0; j < 16; j++) {
        int col = j * 8 + 2 * q;
        if (r0 < M) *(__half2*)&g_bufH[(size_t)r0 * 128 + col] = __floats2half2_rn(d[j][0], d[j][1]);
        if (r1 < M) *(__half2*)&g_bufH[(size_t)r1 * 128 + col] = __floats2half2_rn(d[j][2], d[j][3]);
    }

    // fused attention logits (fp32 accumulators)
#pragma unroll
    for (int hd = 0; hd < 8; hd++) {
        float ss0 = 0.f, ds0 = 0.f, ss1 = 0.f, ds1 = 0.f;
#pragma unroll
        for (int jj = 0; jj < 2; jj++) {
            int j = hd * 2 + jj;
            int c = jj * 8 + 2 * q;
            float as0 = a_src[hd * CH + c], as1 = a_src[hd * CH + c + 1];
            float ad0 = a_dst[hd * CH + c], ad1 = a_dst[hd * CH + c + 1];
            ss0 += d[j][0] * as0 + d[j][1] * as1;
            ds0 += d[j][0] * ad0 + d[j][1] * ad1;
            ss1 += d[j][2] * as0 + d[j][3] * as1;
            ds1 += d[j][2] * ad0 + d[j][3] * ad1;
        }
        ss0 += __shfl_xor_sync(0xffffffffu, ss0, 1);
        ss0 += __shfl_xor_sync(0xffffffffu, ss0, 2);
        ds0 += __shfl_xor_sync(0xffffffffu, ds0, 1);
        ds0 += __shfl_xor_sync(0xffffffffu, ds0, 2);
        ss1 += __shfl_xor_sync(0xffffffffu, ss1, 1);
        ss1 += __shfl_xor_sync(0xffffffffu, ss1, 2);
        ds1 += __shfl_xor_sync(0xffffffffu, ds1, 1);
        ds1 += __shfl_xor_sync(0xffffffffu, ds1, 2);
        if (q == 0) {
            if (r0 < M) { g_alsrc[r0 * 8 + hd] = ss0; g_aldst[r0 * 8 + hd] = ds0; }
            if (r1 < M) { g_alsrc[r1 * 8 + hd] = ss1; g_aldst[r1 * 8 + hd] = ds1; }
        }
    }
}

// ---------------- per-node softmax + aggregation (lean loop, fp16 gather) ----------
__device__ __forceinline__ float4 hload4(int s, int lane) {
    uint2 raw = *(const uint2*)&g_bufH[(size_t)s * FEAT + lane * 4];
    float2 f0 = __half22float2(*(__half2*)&raw.x);
    float2 f1 = __half22float2(*(__half2*)&raw.y);
    return make_float4(f0.x, f0.y, f1.x, f1.y);
}

template <int MODE>
__global__ void k_agg(const float* __restrict__ bias, float* __restrict__ outp,
                      const float* __restrict__ an_w1, const float* __restrict__ an_b1,
                      const float* __restrict__ an_w2, const float* __restrict__ an_b2) {
    int gw = (blockIdx.x * blockDim.x + threadIdx.x) >> 5;
    if (gw >= N_NODES) return;
    int lane = threadIdx.x & 31;
    int d = gw;
    float* __restrict__ out = (MODE == 0) ? (float*)g_bufB : outp;
    const int beg = g_rowptr[d], end = g_rowptr[d + 1];
    const int head = lane >> 2;

    const float adst = g_aldst[d * 8 + head];   // quad-broadcast
    float den;
    float4 acc;
    {   // self loop
        float p = __expf(lrelu02(g_alsrc[d * 8 + head] + adst));
        den = p;
        float4 hv = hload4(d, lane);
        acc.x = hv.x * p; acc.y = hv.y * p; acc.z = hv.z * p; acc.w = hv.w * p;
    }
    int i = beg;
    for (; i + 4 <= end; i += 4) {
        int s0 = g_col[i], s1 = g_col[i + 1], s2 = g_col[i + 2], s3 = g_col[i + 3];
        float a0 = g_alsrc[s0 * 8 + head];
        float a1 = g_alsrc[s1 * 8 + head];
        float a2 = g_alsrc[s2 * 8 + head];
        float a3 = g_alsrc[s3 * 8 + head];
        float4 h0 = hload4(s0, lane);
        float4 h1 = hload4(s1, lane);
        float4 h2 = hload4(s2, lane);
        float4 h3 = hload4(s3, lane);
        float p0 = __expf(lrelu02(a0 + adst));
        float p1 = __expf(lrelu02(a1 + adst));
        float p2 = __expf(lrelu02(a2 + adst));
        float p3 = __expf(lrelu02(a3 + adst));
        den += (p0 + p1) + (p2 + p3);
        acc.x += h0.x * p0 + h1.x * p1 + h2.x * p2 + h3.x * p3;
        acc.y += h0.y * p0 + h1.y * p1 + h2.y * p2 + h3.y * p3;
        acc.z += h0.z * p0 + h1.z * p1 + h2.z * p2 + h3.z * p3;
        acc.w += h0.w * p0 + h1.w * p1 + h2.w * p2 + h3.w * p3;
    }
    for (; i < end; i++) {
        int s = g_col[i];
        float p = __expf(lrelu02(g_alsrc[s * 8 + head] + adst));
        den += p;
        float4 hv = hload4(s, lane);
        acc.x += hv.x * p; acc.y += hv.y * p; acc.z += hv.z * p; acc.w += hv.w * p;
    }
    float inv = 1.f / den;
    acc.x *= inv; acc.y *= inv; acc.z *= inv; acc.w *= inv;

    if (MODE == 0) {
        float4 bb = *(const float4*)&bias[lane * 4];
        acc.x = elu1(acc.x + bb.x);
        acc.y = elu1(acc.y + bb.y);
        acc.z = elu1(acc.z + bb.z);
        acc.w = elu1(acc.w + bb.w);
        *(float4*)&out[(size_t)d * FEAT + lane * 4] = acc;
    } else {
#pragma unroll
        for (int off = 4; off <= 16; off <<= 1) {
            acc.x += __shfl_xor_sync(0xffffffffu, acc.x, off);
            acc.y += __shfl_xor_sync(0xffffffffu, acc.y, off);
            acc.z += __shfl_xor_sync(0xffffffffu, acc.z, off);
            acc.w += __shfl_xor_sync(0xffffffffu, acc.w, off);
        }
        float4 bb = *(const float4*)&bias[(lane & 3) * 4];
        float4 r;
        r.x = acc.x * 0.125f + bb.x;
        r.y = acc.y * 0.125f + bb.y;
        r.z = acc.z * 0.125f + bb.z;
        r.w = acc.w * 0.125f + bb.w;
        if (lane < 4) *(float4*)&out[(size_t)d * CH + lane * 4] = r;

        // fused anomaly head: 16 -> 32 relu -> 1 sigmoid
        float hv[16];
#pragma unroll
        for (int c = 0; c < 16; c++) {
            float comp = ((c & 3) == 0) ? r.x : ((c & 3) == 1) ? r.y
                        : ((c & 3) == 2) ? r.z : r.w;
            hv[c] = __shfl_sync(0xffffffffu, comp, c >> 2);
        }
        float t = an_b1[lane];
#pragma unroll
        for (int c = 0; c < 16; c++) t += hv[c] * an_w1[c * 32 + lane];
        float contrib = fmaxf(t, 0.f) * an_w2[lane];
#pragma unroll
        for (int off = 16; off >= 1; off >>= 1)
            contrib += __shfl_xor_sync(0xffffffffu, contrib, off);
        if (lane == 0)
            out[800000 + d] = 1.f / (1.f + __expf(-(contrib + an_b2[0])));
    }
}

// ---------------- graph mean ----------------
__global__ void k_gsum(const float* __restrict__ hout) {
    __shared__ float sh[256];
    int tid = threadIdx.x;
    float s = 0.f;
    size_t total = (size_t)N_NODES * 16;
    size_t stride = (size_t)gridDim.x * 256;
    for (size_t idx = (size_t)blockIdx.x * 256 + tid; idx < total; idx += stride)
        s += hout[idx];
    sh[tid] = s;
    __syncthreads();
    for (int off = 128; off >= 16; off >>= 1) {
        if (tid < off) sh[tid] += sh[tid + off];
        __syncthreads();
    }
    if (tid < 16) atomicAdd(&g_gsum[tid], sh[tid]);
}

// ---------------- graph classifier ----------------
__global__ void k_final(const float* __restrict__ w1, const float* __restrict__ b1,
                        const float* __restrict__ w2, const float* __restrict__ b2,
                        float* __restrict__ out) {
    __shared__ float emb[16];
    __shared__ float hid[64];
    int t = threadIdx.x;
    if (t < 16) {
        float e = g_gsum[t] * (1.f / (float)N_NODES);
        emb[t] = e;
        out[850000 + t] = e;
    }
    __syncthreads();
    float s = b1[t];
#pragma unroll
    for (int c = 0; c < 16; c++) s += emb[c] * w1[c * 64 + t];
    hid[t] = fmaxf(s, 0.f);
    __syncthreads();
    if (t < 2) {
        float r = b2[t];
#pragma unroll
        for (int u = 0; u < 64; u++) r += hid[u] * w2[u * 2 + t];
        out[850016 + t] = r;
    }
}

// ---------------- launch ----------------
extern "C" void kernel_launch(void* const* d_in, const int* in_sizes, int n_in,
                              void* d_out, int out_size) {
    const float* x      = (const float*)d_in[0];
    const void*  ei     = d_in[1];
    const float* W1     = (const float*)d_in[2];
    const float* a1s    = (const float*)d_in[3];
    const float* a1d    = (const float*)d_in[4];
    const float* b1     = (const float*)d_in[5];
    const float* W2     = (const float*)d_in[6];
    const float* a2s    = (const float*)d_in[7];
    const float* a2d    = (const float*)d_in[8];
    const float* b2     = (const float*)d_in[9];
    const float* W3     = (const float*)d_in[10];
    const float* a3s    = (const float*)d_in[11];
    const float* a3d    = (const float*)d_in[12];
    const float* b3     = (const float*)d_in[13];
    const float* cls_w1 = (const float*)d_in[14];
    const float* cls_b1 = (const float*)d_in[15];
    const float* cls_w2 = (const float*)d_in[16];
    const float* cls_b2 = (const float*)d_in[17];
    const float* an_w1  = (const float*)d_in[18];
    const float* an_b1  = (const float*)d_in[19];
    const float* an_w2  = (const float*)d_in[20];
    const float* an_b2  = (const float*)d_in[21];
    float* out = (float*)d_out;

    const int TB = 256;
    const int nodeBlocks = (N_NODES + TB - 1) / TB;
    const int edgeBlocks = (N_EDGES + TB - 1) / TB;
    const int aggBlocks  = (N_NODES * 32 + TB - 1) / TB;
    const int gemmBlocks = (N_NODES + 127) / 128;  // 391
    const int nchunks    = (N_NODES + 1023) / 1024;

    // layer-1 GEMM kept in the profiled slot (4th launch)
    k_detect<<<1, 1024>>>((const unsigned int*)ei);
    k_zero<<<nodeBlocks, TB>>>();
    k_count<<<edgeBlocks, TB>>>(ei);
    k_gemm<0><<<gemmBlocks, TB>>>(x, W1, a1s, a1d, N_NODES, 256);   // profiled
    k_scan1<<<nchunks, 1024>>>();
    k_scan2<<<1, 32>>>(nchunks);
    k_scan3<<<nodeBlocks, TB>>>();
    k_scatter<<<edgeBlocks, TB>>>(ei);

    k_agg<0><<<aggBlocks, TB>>>(b1, nullptr, nullptr, nullptr, nullptr, nullptr);

    k_gemm<1><<<gemmBlocks, TB>>>(nullptr, W2, a2s, a2d, N_NODES, 128);
    k_agg<0><<<aggBlocks, TB>>>(b2, nullptr, nullptr, nullptr, nullptr, nullptr);

    k_gemm<1><<<gemmBlocks, TB>>>(nullptr, W3, a3s, a3d, N_NODES, 128);
    k_agg<1><<<aggBlocks, TB>>>(b3, out, an_w1, an_b1, an_w2, an_b2);

    k_gsum<<<64, TB>>>(out);
    k_final<<<1, 64>>>(cls_w1, cls_b1, cls_w2, cls_b2, out);
}

// round 14
// speedup vs baseline: 1.5564x; 1.0035x over previous
#include <cuda_runtime.h>
#include <cuda_bf16.h>
#include <cuda_fp16.h>
#include <math.h>

#define N_NODES 50000
#define N_EDGES 800000
#define FEAT    128
#define HEADS   8
#define CH      16

// ---------------- scratch (no allocs; referenced ONLY from device code) ----------
static __device__ __align__(16) __half g_bufH[(size_t)N_NODES * FEAT];  // h (fp16)
static __device__ __align__(16) float  g_bufB[(size_t)N_NODES * FEAT];  // agg out (fp32)
static __device__ float g_alsrc[N_NODES * HEADS];
static __device__ float g_aldst[N_NODES * HEADS];
static __device__ int   g_rowptr[N_NODES + 1];
static __device__ int   g_cnt[N_NODES];
static __device__ int   g_fill[N_NODES];
static __device__ int   g_col[N_EDGES];
static __device__ int   g_incl[N_NODES];
static __device__ int   g_bsum[64];
static __device__ float g_gsum[16];
static __device__ int   g_is64;

__device__ __forceinline__ float lrelu02(float x) { return x > 0.f ? x : 0.2f * x; }
__device__ __forceinline__ float elu1(float x)    { return x > 0.f ? x : (__expf(x) - 1.f); }
__device__ __forceinline__ int   clampN(int v)    { return v < 0 ? 0 : (v >= N_NODES ? N_NODES - 1 : v); }

__device__ __forceinline__ int load_src(const void* eiv, int e) {
    return clampN(g_is64 ? (int)((const long long*)eiv)[e] : ((const int*)eiv)[e]);
}
__device__ __forceinline__ int load_dst(const void* eiv, int e) {
    return clampN(g_is64 ? (int)((const long long*)eiv)[N_EDGES + e]
                         : ((const int*)eiv)[N_EDGES + e]);
}

// ---------------- CSR build ----------------
// k_zero also hosts the edge-dtype probe (block 0): int64 ids < 2^31 -> odd
// 32-bit words are all zero; OR over 512 odd words decides.
__global__ void k_zero(const unsigned int* __restrict__ w) {
    int i = blockIdx.x * blockDim.x + threadIdx.x;
    if (i < N_NODES) { g_cnt[i] = 0; g_fill[i] = 0; }
    if (i < 16) g_gsum[i] = 0.f;
    if (blockIdx.x == 0) {
        __shared__ unsigned int sh[256];
        int t = threadIdx.x;
        sh[t] = w[2 * t + 1] | w[2 * (t + 256) + 1];
        __syncthreads();
        for (int off = 128; off > 0; off >>= 1) {
            if (t < off) sh[t] |= sh[t + off];
            __syncthreads();
        }
        if (t == 0) g_is64 = (sh[0] == 0u) ? 1 : 0;
    }
}

__global__ void k_count(const void* __restrict__ eiv) {
    int e = blockIdx.x * blockDim.x + threadIdx.x;
    if (e >= N_EDGES) return;
    atomicAdd(&g_cnt[load_dst(eiv, e)], 1);
}

__global__ void k_scan1() {
    __shared__ int sh[1024];
    int t = threadIdx.x;
    int g = blockIdx.x * 1024 + t;
    int v = (g < N_NODES) ? g_cnt[g] : 0;
    sh[t] = v;
    __syncthreads();
    for (int off = 1; off < 1024; off <<= 1) {
        int add = (t >= off) ? sh[t - off] : 0;
        __syncthreads();
        sh[t] += add;
        __syncthreads();
    }
    if (g < N_NODES) g_incl[g] = sh[t];
    if (t == 1023) g_bsum[blockIdx.x] = sh[1023];  // raw chunk total
}

// scan3 does the 49-chunk carry scan itself (scan2 eliminated)
__global__ void k_scan3() {
    __shared__ int pre[64];
    if (threadIdx.x == 0) {
        int acc = 0;
        for (int j = 0; j < 49; j++) { pre[j] = acc; acc += g_bsum[j]; }
    }
    __syncthreads();
    int i = blockIdx.x * blockDim.x + threadIdx.x;
    if (i >= N_NODES) return;
    g_rowptr[i + 1] = g_incl[i] + pre[i >> 10];
    if (i == 0) g_rowptr[0] = 0;
}

__global__ void k_scatter(const void* __restrict__ eiv) {
    int e = blockIdx.x * blockDim.x + threadIdx.x;
    if (e >= N_EDGES) return;
    int d = load_dst(eiv, e);
    int pos = g_rowptr[d] + atomicAdd(&g_fill[d], 1);
    g_col[pos] = load_src(eiv, e);
}

// ---------------- bf16 helpers ----------------
__device__ __forceinline__ void split_bf(float x, float& hi, float& lo) {
    __nv_bfloat16 h = __float2bfloat16(x);
    hi = __bfloat162float(h);
    lo = x - hi;
}
__device__ __forceinline__ unsigned pack_bf2(float x0, float x1) {
    __nv_bfloat162 t = __floats2bfloat162_rn(x0, x1);
    return *(unsigned*)&t;
}
__device__ __forceinline__ void mma16(float* d,
                                      unsigned a0, unsigned a1, unsigned a2, unsigned a3,
                                      unsigned b0, unsigned b1) {
    asm volatile(
        "mma.sync.aligned.m16n8k16.row.col.f32.bf16.bf16.f32 "
        "{%0,%1,%2,%3}, {%4,%5,%6,%7}, {%8,%9}, {%0,%1,%2,%3};\n"
        : "+f"(d[0]), "+f"(d[1]), "+f"(d[2]), "+f"(d[3])
        : "r"(a0), "r"(a1), "r"(a2), "r"(a3), "r"(b0), "r"(b1));
}

// smem layout constants (elements)
#define A_BUF_ELEMS (128 * 40)   // bf16
#define W_BUF_ELEMS (8 * 132)    // uint32
#define GEMM_SMEM_BYTES (2 * A_BUF_ELEMS * 2 * 2 + 2 * W_BUF_ELEMS * 4 * 2)  // 57856

// ---------------- tensor-core GEMM (3xBF16 k16, double-buffered smem) -------------
// h = A @ W written fp16 to g_bufH; fused logits fp32.
// BM=128, BN=128, BK=16; 8 warps; warp w owns rows w*16..w*16+15, all 128 cols.
template <int SRC>
__global__ __launch_bounds__(256, 2) void k_gemm(const float* __restrict__ Ain,
                                                 const float* __restrict__ W,
                                                 const float* __restrict__ a_src,
                                                 const float* __restrict__ a_dst,
                                                 int M, int K) {
    const float* __restrict__ A = (SRC == 0) ? Ain : (const float*)g_bufB;

    extern __shared__ __align__(16) char smem[];
    __nv_bfloat16* AhS = (__nv_bfloat16*)smem;                 // [2][A_BUF_ELEMS]
    __nv_bfloat16* AlS = AhS + 2 * A_BUF_ELEMS;                // [2][A_BUF_ELEMS]
    unsigned*      WhP = (unsigned*)(AlS + 2 * A_BUF_ELEMS);   // [2][W_BUF_ELEMS]
    unsigned*      WlP = WhP + 2 * W_BUF_ELEMS;                // [2][W_BUF_ELEMS]

    const int tid  = threadIdx.x;
    const int lane = tid & 31;
    const int warp = tid >> 5;
    const int q    = lane & 3;
    const int g    = lane >> 2;
    const int wrow = warp * 16;
    const int row0 = blockIdx.x * 128;

    float d[16][4];
#pragma unroll
    for (int j = 0; j < 16; j++)
#pragma unroll
        for (int i = 0; i < 4; i++) d[j][i] = 0.f;

    const int a_row = tid >> 1;
    const int a_kb  = (tid & 1) * 8;
    const int w_k2  = tid >> 5;
    const int w_nb  = lane * 4;

    const int gr   = row0 + a_row;
    const bool gok = (gr < M);
    const int nkt  = K >> 4;

    float4 av0 = make_float4(0.f, 0.f, 0.f, 0.f), av1 = av0;
    if (gok) {
        av0 = *(const float4*)&A[(size_t)gr * K + a_kb];
        av1 = *(const float4*)&A[(size_t)gr * K + a_kb + 4];
    }
    float4 wv0 = *(const float4*)&W[(size_t)(2 * w_k2) * 128 + w_nb];
    float4 wv1 = *(const float4*)&W[(size_t)(2 * w_k2 + 1) * 128 + w_nb];

    // stage tile 0 into buffer 0
    {
        float f[8] = {av0.x, av0.y, av0.z, av0.w, av1.x, av1.y, av1.z, av1.w};
        float hi[8], lo[8];
#pragma unroll
        for (int i = 0; i < 8; i++) split_bf(f[i], hi[i], lo[i]);
        *(uint4*)&AhS[a_row * 40 + a_kb] =
            make_uint4(pack_bf2(hi[0], hi[1]), pack_bf2(hi[2], hi[3]),
                       pack_bf2(hi[4], hi[5]), pack_bf2(hi[6], hi[7]));
        *(uint4*)&AlS[a_row * 40 + a_kb] =
            make_uint4(pack_bf2(lo[0], lo[1]), pack_bf2(lo[2], lo[3]),
                       pack_bf2(lo[4], lo[5]), pack_bf2(lo[6], lo[7]));
        const float* p0 = (const float*)&wv0;
        const float* p1 = (const float*)&wv1;
#pragma unroll
        for (int i = 0; i < 4; i++) {
            float h0, l0, h1, l1;
            split_bf(p0[i], h0, l0);
            split_bf(p1[i], h1, l1);
            int n = w_nb + i;
            int idx = (n & 7) * 16 + (n >> 3);
            WhP[w_k2 * 132 + idx] = pack_bf2(h0, h1);
            WlP[w_k2 * 132 + idx] = pack_bf2(l0, l1);
        }
    }
    __syncthreads();

    for (int kt = 0; kt < nkt; kt++) {
        const int cur = kt & 1;
        const int nxt = cur ^ 1;
        const __nv_bfloat16* Ahc = AhS + cur * A_BUF_ELEMS;
        const __nv_bfloat16* Alc = AlS + cur * A_BUF_ELEMS;
        const unsigned*      Whc = WhP + cur * W_BUF_ELEMS;
        const unsigned*      Wlc = WlP + cur * W_BUF_ELEMS;

        const bool more = (kt + 1 < nkt);
        if (more) {
            int k0g = (kt + 1) << 4;
            av0 = make_float4(0.f, 0.f, 0.f, 0.f); av1 = av0;
            if (gok) {
                av0 = *(const float4*)&A[(size_t)gr * K + k0g + a_kb];
                av1 = *(const float4*)&A[(size_t)gr * K + k0g + a_kb + 4];
            }
            wv0 = *(const float4*)&W[(size_t)(k0g + 2 * w_k2) * 128 + w_nb];
            wv1 = *(const float4*)&W[(size_t)(k0g + 2 * w_k2 + 1) * 128 + w_nb];
        }

        // compute this tile
        {
            unsigned ah0 = *(const unsigned*)&Ahc[(wrow + g) * 40 + 2 * q];
            unsigned ah1 = *(const unsigned*)&Ahc[(wrow + g + 8) * 40 + 2 * q];
            unsigned ah2 = *(const unsigned*)&Ahc[(wrow + g) * 40 + 2 * q + 8];
            unsigned ah3 = *(const unsigned*)&Ahc[(wrow + g + 8) * 40 + 2 * q + 8];
            unsigned al0 = *(const unsigned*)&Alc[(wrow + g) * 40 + 2 * q];
            unsigned al1 = *(const unsigned*)&Alc[(wrow + g + 8) * 40 + 2 * q];
            unsigned al2 = *(const unsigned*)&Alc[(wrow + g) * 40 + 2 * q + 8];
            unsigned al3 = *(const unsigned*)&Alc[(wrow + g + 8) * 40 + 2 * q + 8];
#pragma unroll
            for (int c = 0; c < 4; c++) {
                uint4 vh0 = *(const uint4*)&Whc[q * 132 + g * 16 + 4 * c];
                uint4 vh1 = *(const uint4*)&Whc[(q + 4) * 132 + g * 16 + 4 * c];
                uint4 vl0 = *(const uint4*)&Wlc[q * 132 + g * 16 + 4 * c];
                uint4 vl1 = *(const uint4*)&Wlc[(q + 4) * 132 + g * 16 + 4 * c];
                const unsigned* b0h = (const unsigned*)&vh0;
                const unsigned* b1h = (const unsigned*)&vh1;
                const unsigned* b0l = (const unsigned*)&vl0;
                const unsigned* b1l = (const unsigned*)&vl1;
#pragma unroll
                for (int e = 0; e < 4; e++) {
                    const int j = c * 4 + e;
                    mma16(d[j], ah0, ah1, ah2, ah3, b0h[e], b1h[e]);
                    mma16(d[j], al0, al1, al2, al3, b0h[e], b1h[e]);
                    mma16(d[j], ah0, ah1, ah2, ah3, b0l[e], b1l[e]);
                }
            }
        }

        // stage next tile into the other buffer (overlaps peers' compute)
        if (more) {
            float f[8] = {av0.x, av0.y, av0.z, av0.w, av1.x, av1.y, av1.z, av1.w};
            float hi[8], lo[8];
#pragma unroll
            for (int i = 0; i < 8; i++) split_bf(f[i], hi[i], lo[i]);
            *(uint4*)&AhS[nxt * A_BUF_ELEMS + a_row * 40 + a_kb] =
                make_uint4(pack_bf2(hi[0], hi[1]), pack_bf2(hi[2], hi[3]),
                           pack_bf2(hi[4], hi[5]), pack_bf2(hi[6], hi[7]));
            *(uint4*)&AlS[nxt * A_BUF_ELEMS + a_row * 40 + a_kb] =
                make_uint4(pack_bf2(lo[0], lo[1]), pack_bf2(lo[2], lo[3]),
                           pack_bf2(lo[4], lo[5]), pack_bf2(lo[6], lo[7]));
            const float* p0 = (const float*)&wv0;
            const float* p1 = (const float*)&wv1;
#pragma unroll
            for (int i = 0; i < 4; i++) {
                float h0, l0, h1, l1;
                split_bf(p0[i], h0, l0);
                split_bf(p1[i], h1, l1);
                int n = w_nb + i;
                int idx = (n & 7) * 16 + (n >> 3);
                WhP[nxt * W_BUF_ELEMS + w_k2 * 132 + idx] = pack_bf2(h0, h1);
                WlP[nxt * W_BUF_ELEMS + w_k2 * 132 + idx] = pack_bf2(l0, l1);
            }
        }
        __syncthreads();
    }

    const int r0 = row0 + wrow + g;
    const int r1 = r0 + 8;

    // write h as fp16 (only the gather reads h)
#pragma unroll
    for (int j = 0; j < 16; j++) {
        int col = j * 8 + 2 * q;
        if (r0 < M) *(__half2*)&g_bufH[(size_t)r0 * 128 + col] = __floats2half2_rn(d[j][0], d[j][1]);
        if (r1 < M) *(__half2*)&g_bufH[(size_t)r1 * 128 + col] = __floats2half2_rn(d[j][2], d[j][3]);
    }

    // fused attention logits (fp32 accumulators)
#pragma unroll
    for (int hd = 0; hd < 8; hd++) {
        float ss0 = 0.f, ds0 = 0.f, ss1 = 0.f, ds1 = 0.f;
#pragma unroll
        for (int jj = 0; jj < 2; jj++) {
            int j = hd * 2 + jj;
            int c = jj * 8 + 2 * q;
            float as0 = a_src[hd * CH + c], as1 = a_src[hd * CH + c + 1];
            float ad0 = a_dst[hd * CH + c], ad1 = a_dst[hd * CH + c + 1];
            ss0 += d[j][0] * as0 + d[j][1] * as1;
            ds0 += d[j][0] * ad0 + d[j][1] * ad1;
            ss1 += d[j][2] * as0 + d[j][3] * as1;
            ds1 += d[j][2] * ad0 + d[j][3] * ad1;
        }
        ss0 += __shfl_xor_sync(0xffffffffu, ss0, 1);
        ss0 += __shfl_xor_sync(0xffffffffu, ss0, 2);
        ds0 += __shfl_xor_sync(0xffffffffu, ds0, 1);
        ds0 += __shfl_xor_sync(0xffffffffu, ds0, 2);
        ss1 += __shfl_xor_sync(0xffffffffu, ss1, 1);
        ss1 += __shfl_xor_sync(0xffffffffu, ss1, 2);
        ds1 += __shfl_xor_sync(0xffffffffu, ds1, 1);
        ds1 += __shfl_xor_sync(0xffffffffu, ds1, 2);
        if (q == 0) {
            if (r0 < M) { g_alsrc[r0 * 8 + hd] = ss0; g_aldst[r0 * 8 + hd] = ds0; }
            if (r1 < M) { g_alsrc[r1 * 8 + hd] = ss1; g_aldst[r1 * 8 + hd] = ds1; }
        }
    }
}

// ---------------- per-node softmax + aggregation (lean loop, fp16 gather) ----------
__device__ __forceinline__ float4 hload4(int s, int lane) {
    uint2 raw = *(const uint2*)&g_bufH[(size_t)s * FEAT + lane * 4];
    float2 f0 = __half22float2(*(__half2*)&raw.x);
    float2 f1 = __half22float2(*(__half2*)&raw.y);
    return make_float4(f0.x, f0.y, f1.x, f1.y);
}

template <int MODE>
__global__ void k_agg(const float* __restrict__ bias, float* __restrict__ outp,
                      const float* __restrict__ an_w1, const float* __restrict__ an_b1,
                      const float* __restrict__ an_w2, const float* __restrict__ an_b2) {
    int gw = (blockIdx.x * blockDim.x + threadIdx.x) >> 5;
    if (gw >= N_NODES) return;
    int lane = threadIdx.x & 31;
    int d = gw;
    float* __restrict__ out = (MODE == 0) ? (float*)g_bufB : outp;
    const int beg = g_rowptr[d], end = g_rowptr[d + 1];
    const int head = lane >> 2;

    const float adst = g_aldst[d * 8 + head];
    float den;
    float4 acc;
    {   // self loop
        float p = __expf(lrelu02(g_alsrc[d * 8 + head] + adst));
        den = p;
        float4 hv = hload4(d, lane);
        acc.x = hv.x * p; acc.y = hv.y * p; acc.z = hv.z * p; acc.w = hv.w * p;
    }
    int i = beg;
    for (; i + 4 <= end; i += 4) {
        int s0 = g_col[i], s1 = g_col[i + 1], s2 = g_col[i + 2], s3 = g_col[i + 3];
        float a0 = g_alsrc[s0 * 8 + head];
        float a1 = g_alsrc[s1 * 8 + head];
        float a2 = g_alsrc[s2 * 8 + head];
        float a3 = g_alsrc[s3 * 8 + head];
        float4 h0 = hload4(s0, lane);
        float4 h1 = hload4(s1, lane);
        float4 h2 = hload4(s2, lane);
        float4 h3 = hload4(s3, lane);
        float p0 = __expf(lrelu02(a0 + adst));
        float p1 = __expf(lrelu02(a1 + adst));
        float p2 = __expf(lrelu02(a2 + adst));
        float p3 = __expf(lrelu02(a3 + adst));
        den += (p0 + p1) + (p2 + p3);
        acc.x += h0.x * p0 + h1.x * p1 + h2.x * p2 + h3.x * p3;
        acc.y += h0.y * p0 + h1.y * p1 + h2.y * p2 + h3.y * p3;
        acc.z += h0.z * p0 + h1.z * p1 + h2.z * p2 + h3.z * p3;
        acc.w += h0.w * p0 + h1.w * p1 + h2.w * p2 + h3.w * p3;
    }
    for (; i < end; i++) {
        int s = g_col[i];
        float p = __expf(lrelu02(g_alsrc[s * 8 + head] + adst));
        den += p;
        float4 hv = hload4(s, lane);
        acc.x += hv.x * p; acc.y += hv.y * p; acc.z += hv.z * p; acc.w += hv.w * p;
    }
    float inv = 1.f / den;
    acc.x *= inv; acc.y *= inv; acc.z *= inv; acc.w *= inv;

    if (MODE == 0) {
        float4 bb = *(const float4*)&bias[lane * 4];
        acc.x = elu1(acc.x + bb.x);
        acc.y = elu1(acc.y + bb.y);
        acc.z = elu1(acc.z + bb.z);
        acc.w = elu1(acc.w + bb.w);
        *(float4*)&out[(size_t)d * FEAT + lane * 4] = acc;
    } else {
#pragma unroll
        for (int off = 4; off <= 16; off <<= 1) {
            acc.x += __shfl_xor_sync(0xffffffffu, acc.x, off);
            acc.y += __shfl_xor_sync(0xffffffffu, acc.y, off);
            acc.z += __shfl_xor_sync(0xffffffffu, acc.z, off);
            acc.w += __shfl_xor_sync(0xffffffffu, acc.w, off);
        }
        float4 bb = *(const float4*)&bias[(lane & 3) * 4];
        float4 r;
        r.x = acc.x * 0.125f + bb.x;
        r.y = acc.y * 0.125f + bb.y;
        r.z = acc.z * 0.125f + bb.z;
        r.w = acc.w * 0.125f + bb.w;
        if (lane < 4) *(float4*)&out[(size_t)d * CH + lane * 4] = r;

        // fused anomaly head: 16 -> 32 relu -> 1 sigmoid
        float hv[16];
#pragma unroll
        for (int c = 0; c < 16; c++) {
            float comp = ((c & 3) == 0) ? r.x : ((c & 3) == 1) ? r.y
                        : ((c & 3) == 2) ? r.z : r.w;
            hv[c] = __shfl_sync(0xffffffffu, comp, c >> 2);
        }
        float t = an_b1[lane];
#pragma unroll
        for (int c = 0; c < 16; c++) t += hv[c] * an_w1[c * 32 + lane];
        float contrib = fmaxf(t, 0.f) * an_w2[lane];
#pragma unroll
        for (int off = 16; off >= 1; off >>= 1)
            contrib += __shfl_xor_sync(0xffffffffu, contrib, off);
        if (lane == 0)
            out[800000 + d] = 1.f / (1.f + __expf(-(contrib + an_b2[0])));
    }
}

// ---------------- graph mean ----------------
__global__ void k_gsum(const float* __restrict__ hout) {
    __shared__ float sh[256];
    int tid = threadIdx.x;
    float s = 0.f;
    size_t total = (size_t)N_NODES * 16;
    size_t stride = (size_t)gridDim.x * 256;
    for (size_t idx = (size_t)blockIdx.x * 256 + tid; idx < total; idx += stride)
        s += hout[idx];
    sh[tid] = s;
    __syncthreads();
    for (int off = 128; off >= 16; off >>= 1) {
        if (tid < off) sh[tid] += sh[tid + off];
        __syncthreads();
    }
    if (tid < 16) atomicAdd(&g_gsum[tid], sh[tid]);
}

// ---------------- graph classifier ----------------
__global__ void k_final(const float* __restrict__ w1, const float* __restrict__ b1,
                        const float* __restrict__ w2, const float* __restrict__ b2,
                        float* __restrict__ out) {
    __shared__ float emb[16];
    __shared__ float hid[64];
    int t = threadIdx.x;
    if (t < 16) {
        float e = g_gsum[t] * (1.f / (float)N_NODES);
        emb[t] = e;
        out[850000 + t] = e;
    }
    __syncthreads();
    float s = b1[t];
#pragma unroll
    for (int c = 0; c < 16; c++) s += emb[c] * w1[c * 64 + t];
    hid[t] = fmaxf(s, 0.f);
    __syncthreads();
    if (t < 2) {
        float r = b2[t];
#pragma unroll
        for (int u = 0; u < 64; u++) r += hid[u] * w2[u * 2 + t];
        out[850016 + t] = r;
    }
}

// ---------------- launch ----------------
extern "C" void kernel_launch(void* const* d_in, const int* in_sizes, int n_in,
                              void* d_out, int out_size) {
    const float* x      = (const float*)d_in[0];
    const void*  ei     = d_in[1];
    const float* W1     = (const float*)d_in[2];
    const float* a1s    = (const float*)d_in[3];
    const float* a1d    = (const float*)d_in[4];
    const float* b1     = (const float*)d_in[5];
    const float* W2     = (const float*)d_in[6];
    const float* a2s    = (const float*)d_in[7];
    const float* a2d    = (const float*)d_in[8];
    const float* b2     = (const float*)d_in[9];
    const float* W3     = (const float*)d_in[10];
    const float* a3s    = (const float*)d_in[11];
    const float* a3d    = (const float*)d_in[12];
    const float* b3     = (const float*)d_in[13];
    const float* cls_w1 = (const float*)d_in[14];
    const float* cls_b1 = (const float*)d_in[15];
    const float* cls_w2 = (const float*)d_in[16];
    const float* cls_b2 = (const float*)d_in[17];
    const float* an_w1  = (const float*)d_in[18];
    const float* an_b1  = (const float*)d_in[19];
    const float* an_w2  = (const float*)d_in[20];
    const float* an_b2  = (const float*)d_in[21];
    float* out = (float*)d_out;

    const int TB = 256;
    const int nodeBlocks = (N_NODES + TB - 1) / TB;
    const int edgeBlocks = (N_EDGES + TB - 1) / TB;
    const int aggBlocks  = (N_NODES * 32 + TB - 1) / TB;
    const int gemmBlocks = (N_NODES + 127) / 128;  // 391
    const int nchunks    = (N_NODES + 1023) / 1024;

    // opt-in dynamic smem for the double-buffered GEMM (idempotent host call)
    cudaFuncSetAttribute(k_gemm<0>, cudaFuncAttributeMaxDynamicSharedMemorySize,
                         GEMM_SMEM_BYTES);
    cudaFuncSetAttribute(k_gemm<1>, cudaFuncAttributeMaxDynamicSharedMemorySize,
                         GEMM_SMEM_BYTES);

    // layer-1 GEMM kept in absolute launch slot #4 (profiled)
    k_zero<<<nodeBlocks, TB>>>((const unsigned int*)ei);
    k_count<<<edgeBlocks, TB>>>(ei);
    k_scan1<<<nchunks, 1024>>>();
    k_gemm<0><<<gemmBlocks, TB, GEMM_SMEM_BYTES>>>(x, W1, a1s, a1d, N_NODES, 256);
    k_scan3<<<nodeBlocks, TB>>>();
    k_scatter<<<edgeBlocks, TB>>>(ei);

    k_agg<0><<<aggBlocks, TB>>>(b1, nullptr, nullptr, nullptr, nullptr, nullptr);

    k_gemm<1><<<gemmBlocks, TB, GEMM_SMEM_BYTES>>>(nullptr, W2, a2s, a2d, N_NODES, 128);
    k_agg<0><<<aggBlocks, TB>>>(b2, nullptr, nullptr, nullptr, nullptr, nullptr);

    k_gemm<1><<<gemmBlocks, TB, GEMM_SMEM_BYTES>>>(nullptr, W3, a3s, a3d, N_NODES, 128);
    k_agg<1><<<aggBlocks, TB>>>(b3, out, an_w1, an_b1, an_w2, an_b2);

    k_gsum<<<64, TB>>>(out);
    k_final<<<1, 64>>>(cls_w1, cls_b1, cls_w2, cls_b2, out);
}